// round 1
// baseline (speedup 1.0000x reference)
#include <cuda_runtime.h>
#include <math.h>
#include <stdint.h>

#define Bb 8
#define Tt 1024
#define Ee 1024
#define Hh 16
#define Dh 64
#define Mm (Bb*Tt)   // 8192

// Scratch (allocation-free rule: __device__ globals)
__device__ float g_Q[Bb*Hh*Tt*Dh];
__device__ float g_K[Bb*Hh*Tt*Dh];
__device__ float g_V[Bb*Hh*Tt*Dh];
__device__ float g_Hid[Bb*Tt*Ee];

// ---------------------------------------------------------------------------
// Kernel 1: QKV projection. C[m,n] = sum_k x[m,k] * W[n/64][k][n%64]
// grid = (N/128=8, M/128=64, 3), block = 256. Output layout [B,H,T,DH].
// ---------------------------------------------------------------------------
__global__ __launch_bounds__(256) void qkv_kernel(
    const float* __restrict__ x,
    const float* __restrict__ Wq,
    const float* __restrict__ Wk,
    const float* __restrict__ Wv)
{
    __shared__ float As[8][132];   // transposed A: As[k][m]
    __shared__ float Bs[8][132];   // Bs[k][n]

    const int m0 = blockIdx.y * 128;
    const int n0 = blockIdx.x * 128;
    const int which = blockIdx.z;
    const float* W = (which == 0) ? Wq : ((which == 1) ? Wk : Wv);
    float* outp    = (which == 0) ? g_Q : ((which == 1) ? g_K : g_V);

    const int tid = threadIdx.x;
    const int ty = tid >> 4, tx = tid & 15;

    const int a_m = tid >> 1;         // 0..127
    const int a_k = (tid & 1) * 4;    // 0 or 4
    const int b_k = tid >> 5;         // 0..7
    const int b_n = (tid & 31) * 4;   // 0..124

    float c[8][8] = {};
    float a[8], bv8[8];

    for (int k0 = 0; k0 < Ee; k0 += 8) {
        float4 av = *(const float4*)(x + (size_t)(m0 + a_m) * Ee + k0 + a_k);
        const int n = n0 + b_n;
        float4 bv = *(const float4*)(W + (size_t)(n >> 6) * (Ee * Dh)
                                       + (size_t)(k0 + b_k) * Dh + (n & 63));
        As[a_k + 0][a_m] = av.x; As[a_k + 1][a_m] = av.y;
        As[a_k + 2][a_m] = av.z; As[a_k + 3][a_m] = av.w;
        *(float4*)&Bs[b_k][b_n] = bv;
        __syncthreads();
#pragma unroll
        for (int kk = 0; kk < 8; ++kk) {
            *(float4*)&a[0]   = *(const float4*)&As[kk][ty * 8];
            *(float4*)&a[4]   = *(const float4*)&As[kk][ty * 8 + 4];
            *(float4*)&bv8[0] = *(const float4*)&Bs[kk][tx * 8];
            *(float4*)&bv8[4] = *(const float4*)&Bs[kk][tx * 8 + 4];
#pragma unroll
            for (int i = 0; i < 8; i++)
#pragma unroll
                for (int j = 0; j < 8; j++)
                    c[i][j] = fmaf(a[i], bv8[j], c[i][j]);
        }
        __syncthreads();
    }

#pragma unroll
    for (int i = 0; i < 8; i++) {
        const int m = m0 + ty * 8 + i;
        const int b = m >> 10, t = m & 1023;
#pragma unroll
        for (int j = 0; j < 8; j++) {
            const int n = n0 + tx * 8 + j;
            const int h = n >> 6, d = n & 63;
            outp[(((size_t)(b * Hh + h)) * Tt + t) * Dh + d] = c[i][j];
        }
    }
}

// ---------------------------------------------------------------------------
// Kernel 2: causal flash attention. grid = (T/128=8, B*H=128), block = 256.
// Per block: 128 Q rows, KV tiles of 64. S = Q K^T and O += P V as
// register-tiled smem GEMMs (16x16 thread grid, 8x4 per thread).
// ---------------------------------------------------------------------------
__global__ __launch_bounds__(256) void attn_kernel()
{
    extern __shared__ float sm[];
    float* Qt = sm;                 // [64][132]  Qt[d][m]
    float* Kt = Qt + 64 * 132;      // [64][68]   Kt[d][key]
    float* Vs = Kt + 64 * 68;       // [64][68]   Vs[key][d]
    float* St = Vs + 64 * 68;       // [64][132]  St[key][m]
    float* rm = St + 64 * 132;      // [128] running max
    float* rl = rm + 128;           // [128] running sum
    float* rs = rl + 128;           // [128] rescale factor

    const int tid = threadIdx.x;
    const int qi  = blockIdx.x;
    const int bh  = blockIdx.y;           // = b*H + h
    const int qm0 = qi * 128;
    const size_t base = (size_t)bh * Tt * Dh;

    const int ty = tid >> 4, tx = tid & 15;

    // Load Q block transposed: Qt[d][m]
    {
        const int m  = tid & 127;
        const int d0 = (tid >> 7) * 32;
        const float* qrow = g_Q + base + (size_t)(qm0 + m) * Dh + d0;
#pragma unroll
        for (int u = 0; u < 8; u++) {
            float4 v = *(const float4*)(qrow + 4 * u);
            Qt[(d0 + 4 * u + 0) * 132 + m] = v.x;
            Qt[(d0 + 4 * u + 1) * 132 + m] = v.y;
            Qt[(d0 + 4 * u + 2) * 132 + m] = v.z;
            Qt[(d0 + 4 * u + 3) * 132 + m] = v.w;
        }
    }
    if (tid < 128) { rm[tid] = -1e30f; rl[tid] = 0.0f; }

    float o[8][4] = {};
    const int ntiles = 2 * (qi + 1);
    const float scale = 0.125f;   // DH^-0.5

    for (int kt = 0; kt < ntiles; ++kt) {
        const int kv0 = kt * 64;
        __syncthreads();   // protect Kt/Vs reuse; makes Qt/rm init visible on kt=0

        // K transposed: Kt[d][key]
        {
            const int key = tid & 63;
            const int d0  = (tid >> 6) * 16;
            const float* krow = g_K + base + (size_t)(kv0 + key) * Dh + d0;
#pragma unroll
            for (int u = 0; u < 4; u++) {
                float4 v = *(const float4*)(krow + 4 * u);
                Kt[(d0 + 4 * u + 0) * 68 + key] = v.x;
                Kt[(d0 + 4 * u + 1) * 68 + key] = v.y;
                Kt[(d0 + 4 * u + 2) * 68 + key] = v.z;
                Kt[(d0 + 4 * u + 3) * 68 + key] = v.w;
            }
            // V natural: Vs[key][d]
            const int key2 = tid >> 2;
            const int dv0  = (tid & 3) * 16;
            const float* vrow = g_V + base + (size_t)(kv0 + key2) * Dh + dv0;
#pragma unroll
            for (int u = 0; u < 4; u++)
                *(float4*)&Vs[key2 * 68 + dv0 + 4 * u] = *(const float4*)(vrow + 4 * u);
        }
        __syncthreads();

        // GEMM1: s[i][j] = sum_d Qt[d][ty*8+i] * Kt[d][tx*4+j]
        float s[8][4] = {};
#pragma unroll 4
        for (int d = 0; d < 64; ++d) {
            float a[8], b4[4];
            *(float4*)&a[0]  = *(const float4*)&Qt[d * 132 + ty * 8];
            *(float4*)&a[4]  = *(const float4*)&Qt[d * 132 + ty * 8 + 4];
            *(float4*)&b4[0] = *(const float4*)&Kt[d * 68 + tx * 4];
#pragma unroll
            for (int i = 0; i < 8; i++)
#pragma unroll
                for (int j = 0; j < 4; j++)
                    s[i][j] = fmaf(a[i], b4[j], s[i][j]);
        }
        // store masked+scaled scores transposed: St[key][m]
#pragma unroll
        for (int i = 0; i < 8; i++) {
            const int q = qm0 + ty * 8 + i;
#pragma unroll
            for (int j = 0; j < 4; j++) {
                const int k = kv0 + tx * 4 + j;
                St[(tx * 4 + j) * 132 + ty * 8 + i] =
                    (k <= q) ? s[i][j] * scale : -1e30f;
            }
        }
        __syncthreads();

        // Online softmax: 2 threads per row (lanes tid, tid^1)
        {
            const int r  = tid >> 1;
            const int c0 = (tid & 1) * 32;
            float mloc = -1e30f;
#pragma unroll
            for (int c = 0; c < 32; c++)
                mloc = fmaxf(mloc, St[(c0 + c) * 132 + r]);
            mloc = fmaxf(mloc, __shfl_xor_sync(0xffffffffu, mloc, 1));
            const float mprev = rm[r];
            const float mnew  = fmaxf(mprev, mloc);
            const float corr  = __expf(mprev - mnew);
            float ssum = 0.0f;
#pragma unroll
            for (int c = 0; c < 32; c++) {
                float p = __expf(St[(c0 + c) * 132 + r] - mnew);
                St[(c0 + c) * 132 + r] = p;
                ssum += p;
            }
            ssum += __shfl_xor_sync(0xffffffffu, ssum, 1);
            if ((tid & 1) == 0) {
                rm[r] = mnew;
                rl[r] = rl[r] * corr + ssum;
                rs[r] = corr;
            }
        }
        __syncthreads();

        // GEMM2: o = o*corr + P @ V
        float cf[8];
#pragma unroll
        for (int i = 0; i < 8; i++) cf[i] = rs[ty * 8 + i];
#pragma unroll
        for (int i = 0; i < 8; i++)
#pragma unroll
            for (int j = 0; j < 4; j++) o[i][j] *= cf[i];
#pragma unroll 4
        for (int kk = 0; kk < 64; ++kk) {
            float a[8], b4[4];
            *(float4*)&a[0]  = *(const float4*)&St[kk * 132 + ty * 8];
            *(float4*)&a[4]  = *(const float4*)&St[kk * 132 + ty * 8 + 4];
            *(float4*)&b4[0] = *(const float4*)&Vs[kk * 68 + tx * 4];
#pragma unroll
            for (int i = 0; i < 8; i++)
#pragma unroll
                for (int j = 0; j < 4; j++)
                    o[i][j] = fmaf(a[i], b4[j], o[i][j]);
        }
    }

    // Normalize and write [B, T, H*DH]
    const int b = bh / Hh, h = bh % Hh;
    float inv[8];
#pragma unroll
    for (int i = 0; i < 8; i++) inv[i] = 1.0f / rl[ty * 8 + i];
#pragma unroll
    for (int i = 0; i < 8; i++) {
        const int t = qm0 + ty * 8 + i;
#pragma unroll
        for (int j = 0; j < 4; j++) {
            const int d = tx * 4 + j;
            g_Hid[((size_t)b * Tt + t) * Ee + h * Dh + d] = o[i][j] * inv[i];
        }
    }
}

#define ATTN_SMEM_BYTES ((64*132 + 64*68 + 64*68 + 64*132 + 3*128) * 4)

// ---------------------------------------------------------------------------
// Kernel 3: output projection. C[m,n] = sum_k Hid[m,k]*Wp[n,k] + bp[n]
// grid = (8, 64), block = 256.
// ---------------------------------------------------------------------------
__global__ __launch_bounds__(256) void proj_kernel(
    const float* __restrict__ Wp,
    const float* __restrict__ bp,
    float* __restrict__ out)
{
    __shared__ float As[8][132];
    __shared__ float Bs[8][132];

    const int m0 = blockIdx.y * 128;
    const int n0 = blockIdx.x * 128;

    const int tid = threadIdx.x;
    const int ty = tid >> 4, tx = tid & 15;

    const int a_m = tid >> 1;
    const int a_k = (tid & 1) * 4;
    const int b_n = tid & 127;        // 0..127
    const int b_k = (tid >> 7) * 4;   // 0 or 4

    float c[8][8] = {};
    float a[8], bv8[8];

    for (int k0 = 0; k0 < Ee; k0 += 8) {
        float4 av = *(const float4*)(g_Hid + (size_t)(m0 + a_m) * Ee + k0 + a_k);
        float4 bv = *(const float4*)(Wp + (size_t)(n0 + b_n) * Ee + k0 + b_k);
        As[a_k + 0][a_m] = av.x; As[a_k + 1][a_m] = av.y;
        As[a_k + 2][a_m] = av.z; As[a_k + 3][a_m] = av.w;
        Bs[b_k + 0][b_n] = bv.x; Bs[b_k + 1][b_n] = bv.y;
        Bs[b_k + 2][b_n] = bv.z; Bs[b_k + 3][b_n] = bv.w;
        __syncthreads();
#pragma unroll
        for (int kk = 0; kk < 8; ++kk) {
            *(float4*)&a[0]   = *(const float4*)&As[kk][ty * 8];
            *(float4*)&a[4]   = *(const float4*)&As[kk][ty * 8 + 4];
            *(float4*)&bv8[0] = *(const float4*)&Bs[kk][tx * 8];
            *(float4*)&bv8[4] = *(const float4*)&Bs[kk][tx * 8 + 4];
#pragma unroll
            for (int i = 0; i < 8; i++)
#pragma unroll
                for (int j = 0; j < 8; j++)
                    c[i][j] = fmaf(a[i], bv8[j], c[i][j]);
        }
        __syncthreads();
    }

#pragma unroll
    for (int i = 0; i < 8; i++) {
        const int m = m0 + ty * 8 + i;
#pragma unroll
        for (int j = 0; j < 8; j++) {
            const int n = n0 + tx * 8 + j;
            out[(size_t)m * Ee + n] = c[i][j] + bp[n];
        }
    }
}

// ---------------------------------------------------------------------------
extern "C" void kernel_launch(void* const* d_in, const int* in_sizes, int n_in,
                              void* d_out, int out_size)
{
    const float* x  = (const float*)d_in[0];
    const float* Wq = (const float*)d_in[1];
    const float* Wk = (const float*)d_in[2];
    const float* Wv = (const float*)d_in[3];
    const float* Wp = (const float*)d_in[4];
    const float* bp = (const float*)d_in[5];
    float* out = (float*)d_out;

    cudaFuncSetAttribute(attn_kernel,
                         cudaFuncAttributeMaxDynamicSharedMemorySize,
                         ATTN_SMEM_BYTES);

    // 1) QKV projections
    {
        dim3 grid((Hh * Dh) / 128, Mm / 128, 3);
        qkv_kernel<<<grid, 256>>>(x, Wq, Wk, Wv);
    }
    // 2) causal attention
    {
        dim3 grid(Tt / 128, Bb * Hh);
        attn_kernel<<<grid, 256, ATTN_SMEM_BYTES>>>();
    }
    // 3) output projection + bias
    {
        dim3 grid(Ee / 128, Mm / 128);
        proj_kernel<<<grid, 256>>>(Wp, bp, out);
    }
}

// round 3
// speedup vs baseline: 1.6390x; 1.6390x over previous
#include <cuda_runtime.h>
#include <math.h>
#include <stdint.h>

#define Bb 8
#define Tt 1024
#define Ee 1024
#define Hh 16
#define Dh 64
#define Mm (Bb*Tt)   // 8192

// Scratch (allocation-free rule: __device__ globals)
__device__ float g_Q[Bb*Hh*Tt*Dh];
__device__ float g_K[Bb*Hh*Tt*Dh];
__device__ float g_V[Bb*Hh*Tt*Dh];
__device__ float g_Hid[Bb*Tt*Ee];

// ============================ helpers ============================
__device__ __forceinline__ uint32_t smem_u32(const void* p) {
    uint32_t a;
    asm("{ .reg .u64 t; cvta.to.shared.u64 t, %1; cvt.u32.u64 %0, t; }"
        : "=r"(a) : "l"(p));
    return a;
}
__device__ __forceinline__ uint32_t f2tf32(float x) {
    uint32_t r;
    asm("cvt.rna.tf32.f32 %0, %1;" : "=r"(r) : "f"(x));
    return r;
}
#define ST4U(addr, a, b, c, d) \
    asm volatile("st.shared.v4.b32 [%0], {%1, %2, %3, %4};" \
                 :: "r"(addr), "r"(a), "r"(b), "r"(c), "r"(d) : "memory")
#define LDSM_X4(r0, r1, r2, r3, addr) \
    asm volatile("ldmatrix.sync.aligned.m8n8.x4.shared.b16 {%0,%1,%2,%3}, [%4];" \
                 : "=r"(r0), "=r"(r1), "=r"(r2), "=r"(r3) : "r"(addr))

__device__ __forceinline__ void mma_tf32(float* d, const uint32_t* a,
                                         uint32_t b0, uint32_t b1) {
    asm volatile(
        "mma.sync.aligned.m16n8k8.row.col.f32.tf32.tf32.f32 "
        "{%0,%1,%2,%3}, {%4,%5,%6,%7}, {%8,%9}, {%0,%1,%2,%3};"
        : "+f"(d[0]), "+f"(d[1]), "+f"(d[2]), "+f"(d[3])
        : "r"(a[0]), "r"(a[1]), "r"(a[2]), "r"(a[3]), "r"(b0), "r"(b1));
}

// ---------------------------------------------------------------------------
// mma.sync tf32 GEMM. 128x128 CTA tile, 8 warps (2x4), warp tile 64x32,
// K-chunk 32. MODE 0: QKV (B = W[h][k][d], out [B,H,T,DH]).
//               MODE 3: proj (B = Wp[n][k], +bias, out [M,E]).
// ---------------------------------------------------------------------------
#define PITCH 36

template <int MODE>
__device__ __forceinline__ void gemm_mma_body(
    const float* __restrict__ A, const float* __restrict__ Wsrc,
    const float* __restrict__ bp, float* __restrict__ outp,
    int m0, int n0)
{
    __shared__ uint32_t As[128][PITCH];
    __shared__ uint32_t Bs[128][PITCH];

    const int tid = threadIdx.x;
    const int lane = tid & 31;
    const int wid = tid >> 5;
    const int warp_m = wid & 1;   // 0..1  -> 64 rows each
    const int warp_n = wid >> 1;  // 0..3  -> 32 cols each

    float acc[4][4][4] = {};      // [mt][nt][reg]

    // ---- per-thread global-load assignment: row = tid>>1, k half = 16*(tid&1)
    const int lm = tid >> 1;
    const int lk = (tid & 1) * 16;

    // ---- ldmatrix source addresses (bytes, shared space)
    const uint32_t a_frag =
        smem_u32(&As[warp_m * 64 + (lane & 15)][(lane >> 4) * 4]);
    const uint32_t b_frag =
        smem_u32(&Bs[warp_n * 32 + (lane & 7) + ((lane >> 4) << 3)]
                    [((lane >> 3) & 1) * 4]);
    const uint32_t a_sts = smem_u32(&As[lm][lk]);
    const uint32_t b_sts = smem_u32(&Bs[lm][lk]);

    uint32_t areg[16], breg[16];

    // ---------------- chunk loader (global -> regs, tf32) ----------------
    auto load_chunk = [&](int c) {
        const int k0 = c * 32;
        const float* ap = A + (size_t)(m0 + lm) * Ee + k0 + lk;
#pragma unroll
        for (int j = 0; j < 4; ++j) {
            float4 v = *(const float4*)(ap + 4 * j);
            areg[4 * j + 0] = f2tf32(v.x); areg[4 * j + 1] = f2tf32(v.y);
            areg[4 * j + 2] = f2tf32(v.z); areg[4 * j + 3] = f2tf32(v.w);
        }
        if (MODE == 3) {
            const float* wp = Wsrc + (size_t)(n0 + lm) * Ee + k0 + lk;
#pragma unroll
            for (int j = 0; j < 4; ++j) {
                float4 v = *(const float4*)(wp + 4 * j);
                breg[4 * j + 0] = f2tf32(v.x); breg[4 * j + 1] = f2tf32(v.y);
                breg[4 * j + 2] = f2tf32(v.z); breg[4 * j + 3] = f2tf32(v.w);
            }
        } else {
            const int gn = n0 + lm, h = gn >> 6, d = gn & 63;
            const float* wp = Wsrc + (size_t)h * (Ee * Dh)
                                   + (size_t)(k0 + lk) * Dh + d;
#pragma unroll
            for (int j = 0; j < 16; ++j)
                breg[j] = f2tf32(wp[(size_t)j * Dh]);
        }
    };
    auto sts_chunk = [&]() {
#pragma unroll
        for (int j = 0; j < 4; ++j)
            ST4U(a_sts + 16 * j, areg[4 * j], areg[4 * j + 1],
                 areg[4 * j + 2], areg[4 * j + 3]);
#pragma unroll
        for (int j = 0; j < 4; ++j)
            ST4U(b_sts + 16 * j, breg[4 * j], breg[4 * j + 1],
                 breg[4 * j + 2], breg[4 * j + 3]);
    };

    load_chunk(0);
    sts_chunk();
    __syncthreads();

    for (int c = 0; c < 32; ++c) {
        if (c < 31) load_chunk(c + 1);

#pragma unroll
        for (int ks = 0; ks < 4; ++ks) {
            uint32_t af[4][4], bf[2][4];
#pragma unroll
            for (int mt = 0; mt < 4; ++mt)
                LDSM_X4(af[mt][0], af[mt][1], af[mt][2], af[mt][3],
                        a_frag + (uint32_t)(mt * 16 * PITCH + ks * 8) * 4);
#pragma unroll
            for (int nb = 0; nb < 2; ++nb)
                LDSM_X4(bf[nb][0], bf[nb][1], bf[nb][2], bf[nb][3],
                        b_frag + (uint32_t)(nb * 16 * PITCH + ks * 8) * 4);
#pragma unroll
            for (int mt = 0; mt < 4; ++mt)
#pragma unroll
                for (int nt = 0; nt < 4; ++nt)
                    mma_tf32(acc[mt][nt], af[mt],
                             bf[nt >> 1][(nt & 1) * 2],
                             bf[nt >> 1][(nt & 1) * 2 + 1]);
        }
        __syncthreads();
        if (c < 31) sts_chunk();
        __syncthreads();
    }

    // ---------------- epilogue: direct register -> global ----------------
    const int r_base = m0 + warp_m * 64 + (lane >> 2);
    const int c_base = n0 + warp_n * 32 + (lane & 3) * 2;
#pragma unroll
    for (int mt = 0; mt < 4; ++mt) {
#pragma unroll
        for (int nt = 0; nt < 4; ++nt) {
            const int row = r_base + mt * 16;
            const int col = c_base + nt * 8;
            float2 lo = make_float2(acc[mt][nt][0], acc[mt][nt][1]);
            float2 hi = make_float2(acc[mt][nt][2], acc[mt][nt][3]);
            if (MODE == 3) {
                lo.x += bp[col]; lo.y += bp[col + 1];
                hi.x += bp[col]; hi.y += bp[col + 1];
                *(float2*)(outp + (size_t)row * Ee + col) = lo;
                *(float2*)(outp + (size_t)(row + 8) * Ee + col) = hi;
            } else {
                const int h = col >> 6, d = col & 63;
                const int b1_ = row >> 10, t1 = row & 1023;
                const int b2_ = (row + 8) >> 10, t2 = (row + 8) & 1023;
                *(float2*)(outp + (((size_t)(b1_ * Hh + h)) * Tt + t1) * Dh + d) = lo;
                *(float2*)(outp + (((size_t)(b2_ * Hh + h)) * Tt + t2) * Dh + d) = hi;
            }
        }
    }
}

__global__ __launch_bounds__(256, 1) void qkv_mma_kernel(
    const float* __restrict__ x,
    const float* __restrict__ Wq,
    const float* __restrict__ Wk,
    const float* __restrict__ Wv)
{
    const int which = blockIdx.z;
    const float* W = (which == 0) ? Wq : ((which == 1) ? Wk : Wv);
    float* outp    = (which == 0) ? g_Q : ((which == 1) ? g_K : g_V);
    gemm_mma_body<0>(x, W, nullptr, outp, blockIdx.y * 128, blockIdx.x * 128);
}

__global__ __launch_bounds__(256, 1) void proj_mma_kernel(
    const float* __restrict__ Wp,
    const float* __restrict__ bp,
    float* __restrict__ out)
{
    gemm_mma_body<3>(g_Hid, Wp, bp, out, blockIdx.y * 128, blockIdx.x * 128);
}

// ---------------------------------------------------------------------------
// Kernel 2: causal flash attention (SIMT fp32, unchanged).
// grid = (T/128=8, B*H=128), block = 256.
// ---------------------------------------------------------------------------
__global__ __launch_bounds__(256) void attn_kernel()
{
    extern __shared__ float sm[];
    float* Qt = sm;                 // [64][132]  Qt[d][m]
    float* Kt = Qt + 64 * 132;      // [64][68]   Kt[d][key]
    float* Vs = Kt + 64 * 68;       // [64][68]   Vs[key][d]
    float* St = Vs + 64 * 68;       // [64][132]  St[key][m]
    float* rm = St + 64 * 132;      // [128]
    float* rl = rm + 128;           // [128]
    float* rs = rl + 128;           // [128]

    const int tid = threadIdx.x;
    const int qi  = blockIdx.x;
    const int bh  = blockIdx.y;
    const int qm0 = qi * 128;
    const size_t base = (size_t)bh * Tt * Dh;

    const int ty = tid >> 4, tx = tid & 15;

    {
        const int m  = tid & 127;
        const int d0 = (tid >> 7) * 32;
        const float* qrow = g_Q + base + (size_t)(qm0 + m) * Dh + d0;
#pragma unroll
        for (int u = 0; u < 8; u++) {
            float4 v = *(const float4*)(qrow + 4 * u);
            Qt[(d0 + 4 * u + 0) * 132 + m] = v.x;
            Qt[(d0 + 4 * u + 1) * 132 + m] = v.y;
            Qt[(d0 + 4 * u + 2) * 132 + m] = v.z;
            Qt[(d0 + 4 * u + 3) * 132 + m] = v.w;
        }
    }
    if (tid < 128) { rm[tid] = -1e30f; rl[tid] = 0.0f; }

    float o[8][4] = {};
    const int ntiles = 2 * (qi + 1);
    const float scale = 0.125f;

    for (int kt = 0; kt < ntiles; ++kt) {
        const int kv0 = kt * 64;
        __syncthreads();

        {
            const int key = tid & 63;
            const int d0  = (tid >> 6) * 16;
            const float* krow = g_K + base + (size_t)(kv0 + key) * Dh + d0;
#pragma unroll
            for (int u = 0; u < 4; u++) {
                float4 v = *(const float4*)(krow + 4 * u);
                Kt[(d0 + 4 * u + 0) * 68 + key] = v.x;
                Kt[(d0 + 4 * u + 1) * 68 + key] = v.y;
                Kt[(d0 + 4 * u + 2) * 68 + key] = v.z;
                Kt[(d0 + 4 * u + 3) * 68 + key] = v.w;
            }
            const int key2 = tid >> 2;
            const int dv0  = (tid & 3) * 16;
            const float* vrow = g_V + base + (size_t)(kv0 + key2) * Dh + dv0;
#pragma unroll
            for (int u = 0; u < 4; u++)
                *(float4*)&Vs[key2 * 68 + dv0 + 4 * u] = *(const float4*)(vrow + 4 * u);
        }
        __syncthreads();

        float s[8][4] = {};
#pragma unroll 4
        for (int d = 0; d < 64; ++d) {
            float a[8], b4[4];
            *(float4*)&a[0]  = *(const float4*)&Qt[d * 132 + ty * 8];
            *(float4*)&a[4]  = *(const float4*)&Qt[d * 132 + ty * 8 + 4];
            *(float4*)&b4[0] = *(const float4*)&Kt[d * 68 + tx * 4];
#pragma unroll
            for (int i = 0; i < 8; i++)
#pragma unroll
                for (int j = 0; j < 4; j++)
                    s[i][j] = fmaf(a[i], b4[j], s[i][j]);
        }
#pragma unroll
        for (int i = 0; i < 8; i++) {
            const int q = qm0 + ty * 8 + i;
#pragma unroll
            for (int j = 0; j < 4; j++) {
                const int k = kv0 + tx * 4 + j;
                St[(tx * 4 + j) * 132 + ty * 8 + i] =
                    (k <= q) ? s[i][j] * scale : -1e30f;
            }
        }
        __syncthreads();

        {
            const int r  = tid >> 1;
            const int c0 = (tid & 1) * 32;
            float mloc = -1e30f;
#pragma unroll
            for (int c = 0; c < 32; c++)
                mloc = fmaxf(mloc, St[(c0 + c) * 132 + r]);
            mloc = fmaxf(mloc, __shfl_xor_sync(0xffffffffu, mloc, 1));
            const float mprev = rm[r];
            const float mnew  = fmaxf(mprev, mloc);
            const float corr  = __expf(mprev - mnew);
            float ssum = 0.0f;
#pragma unroll
            for (int c = 0; c < 32; c++) {
                float p = __expf(St[(c0 + c) * 132 + r] - mnew);
                St[(c0 + c) * 132 + r] = p;
                ssum += p;
            }
            ssum += __shfl_xor_sync(0xffffffffu, ssum, 1);
            if ((tid & 1) == 0) {
                rm[r] = mnew;
                rl[r] = rl[r] * corr + ssum;
                rs[r] = corr;
            }
        }
        __syncthreads();

        float cf[8];
#pragma unroll
        for (int i = 0; i < 8; i++) cf[i] = rs[ty * 8 + i];
#pragma unroll
        for (int i = 0; i < 8; i++)
#pragma unroll
            for (int j = 0; j < 4; j++) o[i][j] *= cf[i];
#pragma unroll 4
        for (int kk = 0; kk < 64; ++kk) {
            float a[8], b4[4];
            *(float4*)&a[0]  = *(const float4*)&St[kk * 132 + ty * 8];
            *(float4*)&a[4]  = *(const float4*)&St[kk * 132 + ty * 8 + 4];
            *(float4*)&b4[0] = *(const float4*)&Vs[kk * 68 + tx * 4];
#pragma unroll
            for (int i = 0; i < 8; i++)
#pragma unroll
                for (int j = 0; j < 4; j++)
                    o[i][j] = fmaf(a[i], b4[j], o[i][j]);
        }
    }

    const int b = bh / Hh, h = bh % Hh;
    float inv[8];
#pragma unroll
    for (int i = 0; i < 8; i++) inv[i] = 1.0f / rl[ty * 8 + i];
#pragma unroll
    for (int i = 0; i < 8; i++) {
        const int t = qm0 + ty * 8 + i;
#pragma unroll
        for (int j = 0; j < 4; j++) {
            const int d = tx * 4 + j;
            g_Hid[((size_t)b * Tt + t) * Ee + h * Dh + d] = o[i][j] * inv[i];
        }
    }
}

#define ATTN_SMEM_BYTES ((64*132 + 64*68 + 64*68 + 64*132 + 3*128) * 4)

// ---------------------------------------------------------------------------
extern "C" void kernel_launch(void* const* d_in, const int* in_sizes, int n_in,
                              void* d_out, int out_size)
{
    const float* x  = (const float*)d_in[0];
    const float* Wq = (const float*)d_in[1];
    const float* Wk = (const float*)d_in[2];
    const float* Wv = (const float*)d_in[3];
    const float* Wp = (const float*)d_in[4];
    const float* bp = (const float*)d_in[5];
    float* out = (float*)d_out;

    cudaFuncSetAttribute(attn_kernel,
                         cudaFuncAttributeMaxDynamicSharedMemorySize,
                         ATTN_SMEM_BYTES);

    {
        dim3 grid((Hh * Dh) / 128, Mm / 128, 3);
        qkv_mma_kernel<<<grid, 256>>>(x, Wq, Wk, Wv);
    }
    {
        dim3 grid(Tt / 128, Bb * Hh);
        attn_kernel<<<grid, 256, ATTN_SMEM_BYTES>>>();
    }
    {
        dim3 grid(Ee / 128, Mm / 128);
        proj_mma_kernel<<<grid, 256>>>(Wp, bp, out);
    }
}

// round 4
// speedup vs baseline: 2.2582x; 1.3778x over previous
#include <cuda_runtime.h>
#include <math.h>
#include <stdint.h>

#define Bb 8
#define Tt 1024
#define Ee 1024
#define Hh 16
#define Dh 64
#define Mm (Bb*Tt)   // 8192

// Scratch (allocation-free rule: __device__ globals)
__device__ float g_Q[Bb*Hh*Tt*Dh];
__device__ float g_K[Bb*Hh*Tt*Dh];
__device__ float g_V[Bb*Hh*Tt*Dh];
__device__ float g_Hid[Bb*Tt*Ee];

// ============================ helpers ============================
__device__ __forceinline__ uint32_t smem_u32(const void* p) {
    uint32_t a;
    asm("{ .reg .u64 t; cvta.to.shared.u64 t, %1; cvt.u32.u64 %0, t; }"
        : "=r"(a) : "l"(p));
    return a;
}
__device__ __forceinline__ uint32_t f2tf32(float x) {
    uint32_t r;
    asm("cvt.rna.tf32.f32 %0, %1;" : "=r"(r) : "f"(x));
    return r;
}
#define ST4U(addr, a, b, c, d) \
    asm volatile("st.shared.v4.b32 [%0], {%1, %2, %3, %4};" \
                 :: "r"(addr), "r"(a), "r"(b), "r"(c), "r"(d) : "memory")
#define ST2U(addr, a, b) \
    asm volatile("st.shared.v2.b32 [%0], {%1, %2};" \
                 :: "r"(addr), "r"(a), "r"(b) : "memory")
#define STS1(addr, v) \
    asm volatile("st.shared.b32 [%0], %1;" :: "r"(addr), "r"(v) : "memory")
#define LDSM_X4(r0, r1, r2, r3, addr) \
    asm volatile("ldmatrix.sync.aligned.m8n8.x4.shared.b16 {%0,%1,%2,%3}, [%4];" \
                 : "=r"(r0), "=r"(r1), "=r"(r2), "=r"(r3) : "r"(addr))

__device__ __forceinline__ void mma_tf32(float* d, const uint32_t* a,
                                         uint32_t b0, uint32_t b1) {
    asm volatile(
        "mma.sync.aligned.m16n8k8.row.col.f32.tf32.tf32.f32 "
        "{%0,%1,%2,%3}, {%4,%5,%6,%7}, {%8,%9}, {%0,%1,%2,%3};"
        : "+f"(d[0]), "+f"(d[1]), "+f"(d[2]), "+f"(d[3])
        : "r"(a[0]), "r"(a[1]), "r"(a[2]), "r"(a[3]), "r"(b0), "r"(b1));
}

// ---------------------------------------------------------------------------
// mma.sync tf32 GEMM, double-buffered one-sync pipeline.
// 128x128 CTA tile, 8 warps (2x4), warp tile 64x32, K-chunk 32.
// MODE 0: QKV (B = W[h][k][d], out [B,H,T,DH]).  MODE 3: proj (+bias, [M,E]).
// ---------------------------------------------------------------------------
#define GPITCH 36
#define GBUF (128*GPITCH)              // uint32 per operand buffer
#define GSMEM_BYTES (4*GBUF*4)         // A0 B0 A1 B1 = 73728

template <int MODE>
__device__ __forceinline__ void gemm_mma_body(
    const float* __restrict__ A, const float* __restrict__ Wsrc,
    const float* __restrict__ bp, float* __restrict__ outp,
    int m0, int n0)
{
    extern __shared__ uint32_t dsm[];
    const uint32_t sb = smem_u32(dsm);

    const int tid = threadIdx.x;
    const int lane = tid & 31;
    const int wid = tid >> 5;
    const int warp_m = wid & 1;
    const int warp_n = wid >> 1;

    float acc[4][4][4] = {};

    const int lm = tid >> 1;
    const int lk = (tid & 1) * 16;

    const uint32_t a_frag0 = sb +
        ((warp_m * 64 + (lane & 15)) * GPITCH + (lane >> 4) * 4) * 4;
    const uint32_t b_frag0 = sb + GBUF * 4 +
        ((warp_n * 32 + (lane & 7) + ((lane >> 4) << 3)) * GPITCH
         + ((lane >> 3) & 1) * 4) * 4;
    const uint32_t a_sts0 = sb + (lm * GPITCH + lk) * 4;
    const uint32_t b_sts0 = sb + GBUF * 4 + (lm * GPITCH + lk) * 4;

    uint32_t areg[16], breg[16];

    auto load_chunk = [&](int c) {
        const int k0 = c * 32;
        const float* ap = A + (size_t)(m0 + lm) * Ee + k0 + lk;
#pragma unroll
        for (int j = 0; j < 4; ++j) {
            float4 v = *(const float4*)(ap + 4 * j);
            areg[4 * j + 0] = f2tf32(v.x); areg[4 * j + 1] = f2tf32(v.y);
            areg[4 * j + 2] = f2tf32(v.z); areg[4 * j + 3] = f2tf32(v.w);
        }
        if (MODE == 3) {
            const float* wp = Wsrc + (size_t)(n0 + lm) * Ee + k0 + lk;
#pragma unroll
            for (int j = 0; j < 4; ++j) {
                float4 v = *(const float4*)(wp + 4 * j);
                breg[4 * j + 0] = f2tf32(v.x); breg[4 * j + 1] = f2tf32(v.y);
                breg[4 * j + 2] = f2tf32(v.z); breg[4 * j + 3] = f2tf32(v.w);
            }
        } else {
            const int gn = n0 + lm, h = gn >> 6, d = gn & 63;
            const float* wp = Wsrc + (size_t)h * (Ee * Dh)
                                   + (size_t)(k0 + lk) * Dh + d;
#pragma unroll
            for (int j = 0; j < 16; ++j)
                breg[j] = f2tf32(wp[(size_t)j * Dh]);
        }
    };
    auto sts_chunk = [&](int buf) {
        const uint32_t off = (uint32_t)buf * (2 * GBUF * 4);
#pragma unroll
        for (int j = 0; j < 4; ++j)
            ST4U(a_sts0 + off + 16 * j, areg[4 * j], areg[4 * j + 1],
                 areg[4 * j + 2], areg[4 * j + 3]);
#pragma unroll
        for (int j = 0; j < 4; ++j)
            ST4U(b_sts0 + off + 16 * j, breg[4 * j], breg[4 * j + 1],
                 breg[4 * j + 2], breg[4 * j + 3]);
    };

    load_chunk(0);
    sts_chunk(0);
    __syncthreads();

    for (int c = 0; c < 32; ++c) {
        const int p = c & 1;
        if (c < 31) load_chunk(c + 1);   // LDGs overlap with MMAs below

        const uint32_t af_b = a_frag0 + (uint32_t)p * (2 * GBUF * 4);
        const uint32_t bf_b = b_frag0 + (uint32_t)p * (2 * GBUF * 4);
#pragma unroll
        for (int ks = 0; ks < 4; ++ks) {
            uint32_t af[4][4], bf[2][4];
#pragma unroll
            for (int mt = 0; mt < 4; ++mt)
                LDSM_X4(af[mt][0], af[mt][1], af[mt][2], af[mt][3],
                        af_b + (uint32_t)(mt * 16 * GPITCH + ks * 8) * 4);
#pragma unroll
            for (int nb = 0; nb < 2; ++nb)
                LDSM_X4(bf[nb][0], bf[nb][1], bf[nb][2], bf[nb][3],
                        bf_b + (uint32_t)(nb * 16 * GPITCH + ks * 8) * 4);
#pragma unroll
            for (int mt = 0; mt < 4; ++mt)
#pragma unroll
                for (int nt = 0; nt < 4; ++nt)
                    mma_tf32(acc[mt][nt], af[mt],
                             bf[nt >> 1][(nt & 1) * 2],
                             bf[nt >> 1][(nt & 1) * 2 + 1]);
        }
        if (c < 31) sts_chunk(p ^ 1);
        __syncthreads();
    }

    // ---------------- epilogue ----------------
    const int r_base = m0 + warp_m * 64 + (lane >> 2);
    const int c_base = n0 + warp_n * 32 + (lane & 3) * 2;
#pragma unroll
    for (int mt = 0; mt < 4; ++mt) {
#pragma unroll
        for (int nt = 0; nt < 4; ++nt) {
            const int row = r_base + mt * 16;
            const int col = c_base + nt * 8;
            float2 lo = make_float2(acc[mt][nt][0], acc[mt][nt][1]);
            float2 hi = make_float2(acc[mt][nt][2], acc[mt][nt][3]);
            if (MODE == 3) {
                lo.x += bp[col]; lo.y += bp[col + 1];
                hi.x += bp[col]; hi.y += bp[col + 1];
                *(float2*)(outp + (size_t)row * Ee + col) = lo;
                *(float2*)(outp + (size_t)(row + 8) * Ee + col) = hi;
            } else {
                const int h = col >> 6, d = col & 63;
                const int b1_ = row >> 10, t1 = row & 1023;
                const int b2_ = (row + 8) >> 10, t2 = (row + 8) & 1023;
                *(float2*)(outp + (((size_t)(b1_ * Hh + h)) * Tt + t1) * Dh + d) = lo;
                *(float2*)(outp + (((size_t)(b2_ * Hh + h)) * Tt + t2) * Dh + d) = hi;
            }
        }
    }
}

__global__ __launch_bounds__(256, 1) void qkv_mma_kernel(
    const float* __restrict__ x,
    const float* __restrict__ Wq,
    const float* __restrict__ Wk,
    const float* __restrict__ Wv)
{
    const int which = blockIdx.z;
    const float* W = (which == 0) ? Wq : ((which == 1) ? Wk : Wv);
    float* outp    = (which == 0) ? g_Q : ((which == 1) ? g_K : g_V);
    gemm_mma_body<0>(x, W, nullptr, outp, blockIdx.y * 128, blockIdx.x * 128);
}

__global__ __launch_bounds__(256, 1) void proj_mma_kernel(
    const float* __restrict__ Wp,
    const float* __restrict__ bp,
    float* __restrict__ out)
{
    gemm_mma_body<3>(g_Hid, Wp, bp, out, blockIdx.y * 128, blockIdx.x * 128);
}

// ---------------------------------------------------------------------------
// Tensor-core causal flash attention. grid = (8 qtiles, B*H=128), block 256.
// Each warp: 16 q-rows x full 128-key tile (warp-local online softmax).
// S = Q K^T (tf32 mma), P -> per-warp smem, O += P V (tf32 mma).
// ---------------------------------------------------------------------------
#define AQ_PITCH 68
#define AV_PITCH 132
#define ASM_QS 0
#define ASM_KS (128*AQ_PITCH*4)               // 34816
#define ASM_VT (2*128*AQ_PITCH*4)             // 69632
#define ASM_PW (ASM_VT + 64*AV_PITCH*4)       // 103424
#define ASMEM_BYTES (ASM_PW + 8*16*AV_PITCH*4)   // 171008

__global__ __launch_bounds__(256, 1) void attn_mma_kernel()
{
    extern __shared__ uint32_t dsm[];
    const uint32_t sb = smem_u32(dsm);

    const int tid = threadIdx.x;
    const int lane = tid & 31;
    const int wid = tid >> 5;
    const int qi = blockIdx.x;
    const int bh = blockIdx.y;
    const int qm0 = qi * 128;
    const size_t base = (size_t)bh * (Tt * Dh);
    const float scale = 0.125f;

    // ---- stage Q tile (tf32) into Qs[128][68] ----
    {
        const int r = tid >> 1, c0 = (tid & 1) * 32;
        const float* qp = g_Q + base + (size_t)(qm0 + r) * Dh + c0;
        const uint32_t dst = sb + ASM_QS + (r * AQ_PITCH + c0) * 4;
#pragma unroll
        for (int j = 0; j < 8; ++j) {
            float4 v = *(const float4*)(qp + 4 * j);
            ST4U(dst + 16 * j, f2tf32(v.x), f2tf32(v.y), f2tf32(v.z), f2tf32(v.w));
        }
    }

    float m0r = -1e30f, m1r = -1e30f, l0r = 0.0f, l1r = 0.0f;
    float accO[8][4] = {};

    const uint32_t a_frag_q = sb + ASM_QS +
        ((wid * 16 + (lane & 15)) * AQ_PITCH + (lane >> 4) * 4) * 4;
    const uint32_t b_frag_k = sb + ASM_KS +
        (((lane & 7) + ((lane >> 4) << 3)) * AQ_PITCH + ((lane >> 3) & 1) * 4) * 4;
    const uint32_t b_frag_v = sb + ASM_VT +
        (((lane & 7) + ((lane >> 4) << 3)) * AV_PITCH + ((lane >> 3) & 1) * 4) * 4;
    const uint32_t pw_base = sb + ASM_PW + wid * (16 * AV_PITCH * 4);
    const uint32_t a_frag_p = pw_base +
        ((lane & 15) * AV_PITCH + (lane >> 4) * 4) * 4;
    const uint32_t p_sts = pw_base +
        ((lane >> 2) * AV_PITCH + (lane & 3) * 2) * 4;

    const int row0 = qm0 + wid * 16 + (lane >> 2);

    for (int kt = 0; kt <= qi; ++kt) {
        const int kv0 = kt * 128;
        __syncthreads();   // previous tile's reads done; Q staging visible (kt=0)

        // ---- stage K tile (tf32) into Ks[128][68] ----
        {
            const int r = tid >> 1, c0 = (tid & 1) * 32;
            const float* kp = g_K + base + (size_t)(kv0 + r) * Dh + c0;
            const uint32_t dst = sb + ASM_KS + (r * AQ_PITCH + c0) * 4;
#pragma unroll
            for (int j = 0; j < 8; ++j) {
                float4 v = *(const float4*)(kp + 4 * j);
                ST4U(dst + 16 * j, f2tf32(v.x), f2tf32(v.y), f2tf32(v.z), f2tf32(v.w));
            }
        }
        // ---- stage V tile transposed (tf32): Vt[d][key] ----
        {
            const int key = tid & 127, dh = (tid >> 7) * 32;
            const float* vp = g_V + base + (size_t)(kv0 + key) * Dh + dh;
#pragma unroll
            for (int j = 0; j < 8; ++j) {
                float4 v = *(const float4*)(vp + 4 * j);
                const uint32_t d0 = dh + 4 * j;
                STS1(sb + ASM_VT + ((d0 + 0) * AV_PITCH + key) * 4, f2tf32(v.x));
                STS1(sb + ASM_VT + ((d0 + 1) * AV_PITCH + key) * 4, f2tf32(v.y));
                STS1(sb + ASM_VT + ((d0 + 2) * AV_PITCH + key) * 4, f2tf32(v.z));
                STS1(sb + ASM_VT + ((d0 + 3) * AV_PITCH + key) * 4, f2tf32(v.w));
            }
        }
        __syncthreads();

        // ---- S = Q K^T : 16 n-tiles x 8 k-chunks ----
        float s[16][4];
#pragma unroll
        for (int i = 0; i < 16; ++i)
#pragma unroll
            for (int j = 0; j < 4; ++j) s[i][j] = 0.0f;

#pragma unroll
        for (int kc = 0; kc < 8; ++kc) {
            uint32_t aq[4];
            LDSM_X4(aq[0], aq[1], aq[2], aq[3], a_frag_q + kc * 32);
#pragma unroll
            for (int nb = 0; nb < 8; ++nb) {
                uint32_t bk[4];
                LDSM_X4(bk[0], bk[1], bk[2], bk[3],
                        b_frag_k + (uint32_t)nb * (16 * AQ_PITCH * 4) + kc * 32);
                mma_tf32(s[2 * nb],     aq, bk[0], bk[1]);
                mma_tf32(s[2 * nb + 1], aq, bk[2], bk[3]);
            }
        }

        // ---- mask (diagonal tile only) + scale ----
        if (kt == qi) {
#pragma unroll
            for (int nt = 0; nt < 16; ++nt) {
                const int col = kv0 + nt * 8 + (lane & 3) * 2;
                s[nt][0] = (col     <= row0)     ? s[nt][0] * scale : -1e30f;
                s[nt][1] = (col + 1 <= row0)     ? s[nt][1] * scale : -1e30f;
                s[nt][2] = (col     <= row0 + 8) ? s[nt][2] * scale : -1e30f;
                s[nt][3] = (col + 1 <= row0 + 8) ? s[nt][3] * scale : -1e30f;
            }
        } else {
#pragma unroll
            for (int nt = 0; nt < 16; ++nt) {
                s[nt][0] *= scale; s[nt][1] *= scale;
                s[nt][2] *= scale; s[nt][3] *= scale;
            }
        }

        // ---- online softmax (warp-local, quad reductions) ----
        float mx0 = -1e30f, mx1 = -1e30f;
#pragma unroll
        for (int nt = 0; nt < 16; ++nt) {
            mx0 = fmaxf(mx0, fmaxf(s[nt][0], s[nt][1]));
            mx1 = fmaxf(mx1, fmaxf(s[nt][2], s[nt][3]));
        }
        mx0 = fmaxf(mx0, __shfl_xor_sync(0xffffffffu, mx0, 1));
        mx0 = fmaxf(mx0, __shfl_xor_sync(0xffffffffu, mx0, 2));
        mx1 = fmaxf(mx1, __shfl_xor_sync(0xffffffffu, mx1, 1));
        mx1 = fmaxf(mx1, __shfl_xor_sync(0xffffffffu, mx1, 2));

        const float mn0 = fmaxf(m0r, mx0), mn1 = fmaxf(m1r, mx1);
        const float cr0 = __expf(m0r - mn0), cr1 = __expf(m1r - mn1);
        m0r = mn0; m1r = mn1;

        float sm0 = 0.0f, sm1 = 0.0f;
#pragma unroll
        for (int nt = 0; nt < 16; ++nt) {
            float p00 = __expf(s[nt][0] - mn0);
            float p01 = __expf(s[nt][1] - mn0);
            float p10 = __expf(s[nt][2] - mn1);
            float p11 = __expf(s[nt][3] - mn1);
            sm0 += p00 + p01; sm1 += p10 + p11;
            ST2U(p_sts + nt * 32, f2tf32(p00), f2tf32(p01));
            ST2U(p_sts + 8 * AV_PITCH * 4 + nt * 32, f2tf32(p10), f2tf32(p11));
        }
        sm0 += __shfl_xor_sync(0xffffffffu, sm0, 1);
        sm0 += __shfl_xor_sync(0xffffffffu, sm0, 2);
        sm1 += __shfl_xor_sync(0xffffffffu, sm1, 1);
        sm1 += __shfl_xor_sync(0xffffffffu, sm1, 2);
        l0r = l0r * cr0 + sm0;
        l1r = l1r * cr1 + sm1;

#pragma unroll
        for (int dt = 0; dt < 8; ++dt) {
            accO[dt][0] *= cr0; accO[dt][1] *= cr0;
            accO[dt][2] *= cr1; accO[dt][3] *= cr1;
        }
        __syncwarp();

        // ---- O += P V : 8 d-tiles x 16 k-chunks ----
#pragma unroll
        for (int kc = 0; kc < 16; ++kc) {
            uint32_t ap[4];
            LDSM_X4(ap[0], ap[1], ap[2], ap[3], a_frag_p + kc * 32);
#pragma unroll
            for (int nb = 0; nb < 4; ++nb) {
                uint32_t bv[4];
                LDSM_X4(bv[0], bv[1], bv[2], bv[3],
                        b_frag_v + (uint32_t)nb * (16 * AV_PITCH * 4) + kc * 32);
                mma_tf32(accO[2 * nb],     ap, bv[0], bv[1]);
                mma_tf32(accO[2 * nb + 1], ap, bv[2], bv[3]);
            }
        }
    }

    // ---- normalize + write [B, T, H*DH] ----
    const float inv0 = 1.0f / l0r, inv1 = 1.0f / l1r;
    const int b = bh >> 4, h = bh & 15;
    const int t0 = row0;
#pragma unroll
    for (int dt = 0; dt < 8; ++dt) {
        const int d = dt * 8 + (lane & 3) * 2;
        float2 lo = make_float2(accO[dt][0] * inv0, accO[dt][1] * inv0);
        float2 hi = make_float2(accO[dt][2] * inv1, accO[dt][3] * inv1);
        *(float2*)(g_Hid + ((size_t)b * Tt + t0) * Ee + h * Dh + d) = lo;
        *(float2*)(g_Hid + ((size_t)b * Tt + t0 + 8) * Ee + h * Dh + d) = hi;
    }
}

// ---------------------------------------------------------------------------
extern "C" void kernel_launch(void* const* d_in, const int* in_sizes, int n_in,
                              void* d_out, int out_size)
{
    const float* x  = (const float*)d_in[0];
    const float* Wq = (const float*)d_in[1];
    const float* Wk = (const float*)d_in[2];
    const float* Wv = (const float*)d_in[3];
    const float* Wp = (const float*)d_in[4];
    const float* bp = (const float*)d_in[5];
    float* out = (float*)d_out;

    cudaFuncSetAttribute(qkv_mma_kernel,
                         cudaFuncAttributeMaxDynamicSharedMemorySize, GSMEM_BYTES);
    cudaFuncSetAttribute(proj_mma_kernel,
                         cudaFuncAttributeMaxDynamicSharedMemorySize, GSMEM_BYTES);
    cudaFuncSetAttribute(attn_mma_kernel,
                         cudaFuncAttributeMaxDynamicSharedMemorySize, ASMEM_BYTES);

    {
        dim3 grid((Hh * Dh) / 128, Mm / 128, 3);
        qkv_mma_kernel<<<grid, 256, GSMEM_BYTES>>>(x, Wq, Wk, Wv);
    }
    {
        dim3 grid(Tt / 128, Bb * Hh);
        attn_mma_kernel<<<grid, 256, ASMEM_BYTES>>>();
    }
    {
        dim3 grid(Ee / 128, Mm / 128);
        proj_mma_kernel<<<grid, 256, GSMEM_BYTES>>>(Wp, bp, out);
    }
}

// round 5
// speedup vs baseline: 2.6821x; 1.1877x over previous
#include <cuda_runtime.h>
#include <math.h>
#include <stdint.h>

#define Bb 8
#define Tt 1024
#define Ee 1024
#define Hh 16
#define Dh 64
#define Mm (Bb*Tt)   // 8192

// Scratch (allocation-free rule: __device__ globals)
__device__ float g_Q[Bb*Hh*Tt*Dh];
__device__ float g_K[Bb*Hh*Tt*Dh];
__device__ float g_V[Bb*Hh*Tt*Dh];
__device__ float g_Hid[Bb*Tt*Ee];
__device__ float g_Xt[Mm*Ee];        // tf32-rounded x
__device__ float g_Wt[3*Ee*Ee];      // tf32-rounded, transposed [n=h*64+d][k]
__device__ float g_Wpt[Ee*Ee];       // tf32-rounded Wp (already [n][k])

// ============================ helpers ============================
__device__ __forceinline__ uint32_t smem_u32(const void* p) {
    uint32_t a;
    asm("{ .reg .u64 t; cvta.to.shared.u64 t, %1; cvt.u32.u64 %0, t; }"
        : "=r"(a) : "l"(p));
    return a;
}
__device__ __forceinline__ uint32_t f2tf32(float x) {
    uint32_t r;
    asm("cvt.rna.tf32.f32 %0, %1;" : "=r"(r) : "f"(x));
    return r;
}
#define ST4U(addr, a, b, c, d) \
    asm volatile("st.shared.v4.b32 [%0], {%1, %2, %3, %4};" \
                 :: "r"(addr), "r"(a), "r"(b), "r"(c), "r"(d) : "memory")
#define ST2U(addr, a, b) \
    asm volatile("st.shared.v2.b32 [%0], {%1, %2};" \
                 :: "r"(addr), "r"(a), "r"(b) : "memory")
#define STS1(addr, v) \
    asm volatile("st.shared.b32 [%0], %1;" :: "r"(addr), "r"(v) : "memory")
#define LDSM_X4(r0, r1, r2, r3, addr) \
    asm volatile("ldmatrix.sync.aligned.m8n8.x4.shared.b16 {%0,%1,%2,%3}, [%4];" \
                 : "=r"(r0), "=r"(r1), "=r"(r2), "=r"(r3) : "r"(addr))
#define CP16(dst, src) \
    asm volatile("cp.async.cg.shared.global [%0], [%1], 16;" \
                 :: "r"(dst), "l"(src) : "memory")
#define CP_COMMIT() asm volatile("cp.async.commit_group;" ::: "memory")
#define CP_WAIT1()  asm volatile("cp.async.wait_group 1;" ::: "memory")
#define CP_WAIT0()  asm volatile("cp.async.wait_group 0;" ::: "memory")

__device__ __forceinline__ void mma_tf32(float* d, const uint32_t* a,
                                         uint32_t b0, uint32_t b1) {
    asm volatile(
        "mma.sync.aligned.m16n8k8.row.col.f32.tf32.tf32.f32 "
        "{%0,%1,%2,%3}, {%4,%5,%6,%7}, {%8,%9}, {%0,%1,%2,%3};"
        : "+f"(d[0]), "+f"(d[1]), "+f"(d[2]), "+f"(d[3])
        : "r"(a[0]), "r"(a[1]), "r"(a[2]), "r"(a[3]), "r"(b0), "r"(b1));
}

// ---------------------------------------------------------------------------
// Prep kernels (run every launch; ~100MB traffic total, ~15-20us)
// ---------------------------------------------------------------------------
__global__ __launch_bounds__(256) void prep_round_kernel(
    const float* __restrict__ src, float* __restrict__ dst)
{
    const size_t i = ((size_t)blockIdx.x * 256 + threadIdx.x) * 4;
    float4 v = *(const float4*)(src + i);
    uint4 o = make_uint4(f2tf32(v.x), f2tf32(v.y), f2tf32(v.z), f2tf32(v.w));
    *(uint4*)(dst + i) = o;
}

// W[h][k][d] -> Wt[h*64+d][k], tf32-rounded. grid (32 ktiles, 2 dtiles, 48)
__global__ __launch_bounds__(256) void prep_wt_kernel(
    const float* __restrict__ Wq, const float* __restrict__ Wk,
    const float* __restrict__ Wv)
{
    __shared__ float tile[32][33];
    const int which = blockIdx.z >> 4;
    const int h = blockIdx.z & 15;
    const float* Ws = (which == 0) ? Wq : ((which == 1) ? Wk : Wv);
    const int k0 = blockIdx.x * 32;
    const int d0 = blockIdx.y * 32;
    const int tx = threadIdx.x & 31, ty = threadIdx.x >> 5;

#pragma unroll
    for (int j = 0; j < 4; ++j) {
        const int kk = ty + j * 8;
        tile[kk][tx] = Ws[(size_t)h * (Ee * Dh) + (size_t)(k0 + kk) * Dh + d0 + tx];
    }
    __syncthreads();
#pragma unroll
    for (int j = 0; j < 4; ++j) {
        const int dd = ty + j * 8;
        const int n = h * 64 + d0 + dd;
        g_Wt[(size_t)which * (Ee * Ee) + (size_t)n * Ee + k0 + tx] =
            __uint_as_float(f2tf32(tile[tx][dd]));
    }
}

// ---------------------------------------------------------------------------
// NT tf32 GEMM: A[m][k], B[n][k] both row-major, pre-rounded to tf32.
// 128x128 CTA tile, 8 warps (2x4), warp tile 64x32, K-chunk 32,
// 2-stage cp.async pipeline, 2 CTAs/SM.
// MODE 0: out [B,H,T,DH].  MODE 3: +bias, out [M,E].
// ---------------------------------------------------------------------------
#define GPITCH 36
#define GBUF (128*GPITCH)              // uint32 per operand buffer
#define GSMEM_BYTES (4*GBUF*4)         // A0 B0 A1 B1 = 73728

template <int MODE>
__device__ __forceinline__ void gemm_mma_body(
    const float* __restrict__ A, const float* __restrict__ Bgl,
    const float* __restrict__ bp, float* __restrict__ outp,
    int m0, int n0)
{
    extern __shared__ uint32_t dsm[];
    const uint32_t sb = smem_u32(dsm);

    const int tid = threadIdx.x;
    const int lane = tid & 31;
    const int wid = tid >> 5;
    const int warp_m = wid & 1;
    const int warp_n = wid >> 1;

    float acc[4][4][4] = {};

    const uint32_t a_frag0 = sb +
        ((warp_m * 64 + (lane & 15)) * GPITCH + (lane >> 4) * 4) * 4;
    const uint32_t b_frag0 = sb + GBUF * 4 +
        ((warp_n * 32 + (lane & 7) + ((lane >> 4) << 3)) * GPITCH
         + ((lane >> 3) & 1) * 4) * 4;

    // cp.async assignment: 1024 16B segments per operand, 4 per thread
    const int c_row = tid >> 1;          // rows covered in pairs
    const int c_seg = (tid & 1) * 4;     // segment base (0 or 4)

    auto copy_chunk = [&](int c, int buf) {
        const uint32_t off = (uint32_t)buf * (2 * GBUF * 4);
        const int k0 = c * 32;
        const float* asrc = A + (size_t)(m0 + c_row) * Ee + k0 + c_seg * 4;
        const float* bsrc = Bgl + (size_t)(n0 + c_row) * Ee + k0 + c_seg * 4;
        const uint32_t adst = sb + off + (c_row * GPITCH + c_seg * 4) * 4;
        const uint32_t bdst = adst + GBUF * 4;
#pragma unroll
        for (int j = 0; j < 4; ++j) CP16(adst + 16 * j, asrc + 4 * j);
#pragma unroll
        for (int j = 0; j < 4; ++j) CP16(bdst + 16 * j, bsrc + 4 * j);
    };

    copy_chunk(0, 0);
    CP_COMMIT();

    for (int c = 0; c < 32; ++c) {
        const int p = c & 1;
        if (c < 31) { copy_chunk(c + 1, p ^ 1); CP_COMMIT(); CP_WAIT1(); }
        else        { CP_WAIT0(); }
        __syncthreads();

        const uint32_t af_b = a_frag0 + (uint32_t)p * (2 * GBUF * 4);
        const uint32_t bf_b = b_frag0 + (uint32_t)p * (2 * GBUF * 4);
#pragma unroll
        for (int ks = 0; ks < 4; ++ks) {
            uint32_t af[4][4], bf[2][4];
#pragma unroll
            for (int mt = 0; mt < 4; ++mt)
                LDSM_X4(af[mt][0], af[mt][1], af[mt][2], af[mt][3],
                        af_b + (uint32_t)(mt * 16 * GPITCH + ks * 8) * 4);
#pragma unroll
            for (int nb = 0; nb < 2; ++nb)
                LDSM_X4(bf[nb][0], bf[nb][1], bf[nb][2], bf[nb][3],
                        bf_b + (uint32_t)(nb * 16 * GPITCH + ks * 8) * 4);
#pragma unroll
            for (int mt = 0; mt < 4; ++mt)
#pragma unroll
                for (int nt = 0; nt < 4; ++nt)
                    mma_tf32(acc[mt][nt], af[mt],
                             bf[nt >> 1][(nt & 1) * 2],
                             bf[nt >> 1][(nt & 1) * 2 + 1]);
        }
        __syncthreads();
    }

    // ---------------- epilogue ----------------
    const int r_base = m0 + warp_m * 64 + (lane >> 2);
    const int c_base = n0 + warp_n * 32 + (lane & 3) * 2;
#pragma unroll
    for (int mt = 0; mt < 4; ++mt) {
#pragma unroll
        for (int nt = 0; nt < 4; ++nt) {
            const int row = r_base + mt * 16;
            const int col = c_base + nt * 8;
            float2 lo = make_float2(acc[mt][nt][0], acc[mt][nt][1]);
            float2 hi = make_float2(acc[mt][nt][2], acc[mt][nt][3]);
            if (MODE == 3) {
                lo.x += bp[col]; lo.y += bp[col + 1];
                hi.x += bp[col]; hi.y += bp[col + 1];
                *(float2*)(outp + (size_t)row * Ee + col) = lo;
                *(float2*)(outp + (size_t)(row + 8) * Ee + col) = hi;
            } else {
                const int h = col >> 6, d = col & 63;
                const int b1_ = row >> 10, t1 = row & 1023;
                const int b2_ = (row + 8) >> 10, t2 = (row + 8) & 1023;
                *(float2*)(outp + (((size_t)(b1_ * Hh + h)) * Tt + t1) * Dh + d) = lo;
                *(float2*)(outp + (((size_t)(b2_ * Hh + h)) * Tt + t2) * Dh + d) = hi;
            }
        }
    }
}

__global__ __launch_bounds__(256, 2) void qkv_mma_kernel()
{
    const int which = blockIdx.z;
    float* outp = (which == 0) ? g_Q : ((which == 1) ? g_K : g_V);
    gemm_mma_body<0>(g_Xt, g_Wt + (size_t)which * (Ee * Ee), nullptr, outp,
                     blockIdx.y * 128, blockIdx.x * 128);
}

__global__ __launch_bounds__(256, 2) void proj_mma_kernel(
    const float* __restrict__ bp, float* __restrict__ out)
{
    gemm_mma_body<3>(g_Hid, g_Wpt, bp, out, blockIdx.y * 128, blockIdx.x * 128);
}

// ---------------------------------------------------------------------------
// Tensor-core causal flash attention. grid = (8 qtiles, B*H=128), block 256.
// ---------------------------------------------------------------------------
#define AQ_PITCH 68
#define AV_PITCH 132
#define ASM_QS 0
#define ASM_KS (128*AQ_PITCH*4)
#define ASM_VT (2*128*AQ_PITCH*4)
#define ASM_PW (ASM_VT + 64*AV_PITCH*4)
#define ASMEM_BYTES (ASM_PW + 8*16*AV_PITCH*4)   // 171008

__global__ __launch_bounds__(256, 1) void attn_mma_kernel()
{
    extern __shared__ uint32_t dsm[];
    const uint32_t sb = smem_u32(dsm);

    const int tid = threadIdx.x;
    const int lane = tid & 31;
    const int wid = tid >> 5;
    const int qi = blockIdx.x;
    const int bh = blockIdx.y;
    const int qm0 = qi * 128;
    const size_t base = (size_t)bh * (Tt * Dh);
    const float scale = 0.125f;

    {
        const int r = tid >> 1, c0 = (tid & 1) * 32;
        const float* qp = g_Q + base + (size_t)(qm0 + r) * Dh + c0;
        const uint32_t dst = sb + ASM_QS + (r * AQ_PITCH + c0) * 4;
#pragma unroll
        for (int j = 0; j < 8; ++j) {
            float4 v = *(const float4*)(qp + 4 * j);
            ST4U(dst + 16 * j, f2tf32(v.x), f2tf32(v.y), f2tf32(v.z), f2tf32(v.w));
        }
    }

    float m0r = -1e30f, m1r = -1e30f, l0r = 0.0f, l1r = 0.0f;
    float accO[8][4] = {};

    const uint32_t a_frag_q = sb + ASM_QS +
        ((wid * 16 + (lane & 15)) * AQ_PITCH + (lane >> 4) * 4) * 4;
    const uint32_t b_frag_k = sb + ASM_KS +
        (((lane & 7) + ((lane >> 4) << 3)) * AQ_PITCH + ((lane >> 3) & 1) * 4) * 4;
    const uint32_t b_frag_v = sb + ASM_VT +
        (((lane & 7) + ((lane >> 4) << 3)) * AV_PITCH + ((lane >> 3) & 1) * 4) * 4;
    const uint32_t pw_base = sb + ASM_PW + wid * (16 * AV_PITCH * 4);
    const uint32_t a_frag_p = pw_base +
        ((lane & 15) * AV_PITCH + (lane >> 4) * 4) * 4;
    const uint32_t p_sts = pw_base +
        ((lane >> 2) * AV_PITCH + (lane & 3) * 2) * 4;

    const int row0 = qm0 + wid * 16 + (lane >> 2);

    for (int kt = 0; kt <= qi; ++kt) {
        const int kv0 = kt * 128;
        __syncthreads();

        {
            const int r = tid >> 1, c0 = (tid & 1) * 32;
            const float* kp = g_K + base + (size_t)(kv0 + r) * Dh + c0;
            const uint32_t dst = sb + ASM_KS + (r * AQ_PITCH + c0) * 4;
#pragma unroll
            for (int j = 0; j < 8; ++j) {
                float4 v = *(const float4*)(kp + 4 * j);
                ST4U(dst + 16 * j, f2tf32(v.x), f2tf32(v.y), f2tf32(v.z), f2tf32(v.w));
            }
        }
        {
            const int key = tid & 127, dh = (tid >> 7) * 32;
            const float* vp = g_V + base + (size_t)(kv0 + key) * Dh + dh;
#pragma unroll
            for (int j = 0; j < 8; ++j) {
                float4 v = *(const float4*)(vp + 4 * j);
                const uint32_t d0 = dh + 4 * j;
                STS1(sb + ASM_VT + ((d0 + 0) * AV_PITCH + key) * 4, f2tf32(v.x));
                STS1(sb + ASM_VT + ((d0 + 1) * AV_PITCH + key) * 4, f2tf32(v.y));
                STS1(sb + ASM_VT + ((d0 + 2) * AV_PITCH + key) * 4, f2tf32(v.z));
                STS1(sb + ASM_VT + ((d0 + 3) * AV_PITCH + key) * 4, f2tf32(v.w));
            }
        }
        __syncthreads();

        float s[16][4];
#pragma unroll
        for (int i = 0; i < 16; ++i)
#pragma unroll
            for (int j = 0; j < 4; ++j) s[i][j] = 0.0f;

#pragma unroll
        for (int kc = 0; kc < 8; ++kc) {
            uint32_t aq[4];
            LDSM_X4(aq[0], aq[1], aq[2], aq[3], a_frag_q + kc * 32);
#pragma unroll
            for (int nb = 0; nb < 8; ++nb) {
                uint32_t bk[4];
                LDSM_X4(bk[0], bk[1], bk[2], bk[3],
                        b_frag_k + (uint32_t)nb * (16 * AQ_PITCH * 4) + kc * 32);
                mma_tf32(s[2 * nb],     aq, bk[0], bk[1]);
                mma_tf32(s[2 * nb + 1], aq, bk[2], bk[3]);
            }
        }

        if (kt == qi) {
#pragma unroll
            for (int nt = 0; nt < 16; ++nt) {
                const int col = kv0 + nt * 8 + (lane & 3) * 2;
                s[nt][0] = (col     <= row0)     ? s[nt][0] * scale : -1e30f;
                s[nt][1] = (col + 1 <= row0)     ? s[nt][1] * scale : -1e30f;
                s[nt][2] = (col     <= row0 + 8) ? s[nt][2] * scale : -1e30f;
                s[nt][3] = (col + 1 <= row0 + 8) ? s[nt][3] * scale : -1e30f;
            }
        } else {
#pragma unroll
            for (int nt = 0; nt < 16; ++nt) {
                s[nt][0] *= scale; s[nt][1] *= scale;
                s[nt][2] *= scale; s[nt][3] *= scale;
            }
        }

        float mx0 = -1e30f, mx1 = -1e30f;
#pragma unroll
        for (int nt = 0; nt < 16; ++nt) {
            mx0 = fmaxf(mx0, fmaxf(s[nt][0], s[nt][1]));
            mx1 = fmaxf(mx1, fmaxf(s[nt][2], s[nt][3]));
        }
        mx0 = fmaxf(mx0, __shfl_xor_sync(0xffffffffu, mx0, 1));
        mx0 = fmaxf(mx0, __shfl_xor_sync(0xffffffffu, mx0, 2));
        mx1 = fmaxf(mx1, __shfl_xor_sync(0xffffffffu, mx1, 1));
        mx1 = fmaxf(mx1, __shfl_xor_sync(0xffffffffu, mx1, 2));

        const float mn0 = fmaxf(m0r, mx0), mn1 = fmaxf(m1r, mx1);
        const float cr0 = __expf(m0r - mn0), cr1 = __expf(m1r - mn1);
        m0r = mn0; m1r = mn1;

        float sm0 = 0.0f, sm1 = 0.0f;
#pragma unroll
        for (int nt = 0; nt < 16; ++nt) {
            float p00 = __expf(s[nt][0] - mn0);
            float p01 = __expf(s[nt][1] - mn0);
            float p10 = __expf(s[nt][2] - mn1);
            float p11 = __expf(s[nt][3] - mn1);
            sm0 += p00 + p01; sm1 += p10 + p11;
            ST2U(p_sts + nt * 32, f2tf32(p00), f2tf32(p01));
            ST2U(p_sts + 8 * AV_PITCH * 4 + nt * 32, f2tf32(p10), f2tf32(p11));
        }
        sm0 += __shfl_xor_sync(0xffffffffu, sm0, 1);
        sm0 += __shfl_xor_sync(0xffffffffu, sm0, 2);
        sm1 += __shfl_xor_sync(0xffffffffu, sm1, 1);
        sm1 += __shfl_xor_sync(0xffffffffu, sm1, 2);
        l0r = l0r * cr0 + sm0;
        l1r = l1r * cr1 + sm1;

#pragma unroll
        for (int dt = 0; dt < 8; ++dt) {
            accO[dt][0] *= cr0; accO[dt][1] *= cr0;
            accO[dt][2] *= cr1; accO[dt][3] *= cr1;
        }
        __syncwarp();

#pragma unroll
        for (int kc = 0; kc < 16; ++kc) {
            uint32_t ap[4];
            LDSM_X4(ap[0], ap[1], ap[2], ap[3], a_frag_p + kc * 32);
#pragma unroll
            for (int nb = 0; nb < 4; ++nb) {
                uint32_t bv[4];
                LDSM_X4(bv[0], bv[1], bv[2], bv[3],
                        b_frag_v + (uint32_t)nb * (16 * AV_PITCH * 4) + kc * 32);
                mma_tf32(accO[2 * nb],     ap, bv[0], bv[1]);
                mma_tf32(accO[2 * nb + 1], ap, bv[2], bv[3]);
            }
        }
    }

    // normalize + write tf32-rounded (proj consumes pre-rounded A)
    const float inv0 = 1.0f / l0r, inv1 = 1.0f / l1r;
    const int b = bh >> 4, h = bh & 15;
    const int t0 = row0;
#pragma unroll
    for (int dt = 0; dt < 8; ++dt) {
        const int d = dt * 8 + (lane & 3) * 2;
        float2 lo = make_float2(__uint_as_float(f2tf32(accO[dt][0] * inv0)),
                                __uint_as_float(f2tf32(accO[dt][1] * inv0)));
        float2 hi = make_float2(__uint_as_float(f2tf32(accO[dt][2] * inv1)),
                                __uint_as_float(f2tf32(accO[dt][3] * inv1)));
        *(float2*)(g_Hid + ((size_t)b * Tt + t0) * Ee + h * Dh + d) = lo;
        *(float2*)(g_Hid + ((size_t)b * Tt + t0 + 8) * Ee + h * Dh + d) = hi;
    }
}

// ---------------------------------------------------------------------------
extern "C" void kernel_launch(void* const* d_in, const int* in_sizes, int n_in,
                              void* d_out, int out_size)
{
    const float* x  = (const float*)d_in[0];
    const float* Wq = (const float*)d_in[1];
    const float* Wk = (const float*)d_in[2];
    const float* Wv = (const float*)d_in[3];
    const float* Wp = (const float*)d_in[4];
    const float* bp = (const float*)d_in[5];
    float* out = (float*)d_out;

    cudaFuncSetAttribute(qkv_mma_kernel,
                         cudaFuncAttributeMaxDynamicSharedMemorySize, GSMEM_BYTES);
    cudaFuncSetAttribute(proj_mma_kernel,
                         cudaFuncAttributeMaxDynamicSharedMemorySize, GSMEM_BYTES);
    cudaFuncSetAttribute(attn_mma_kernel,
                         cudaFuncAttributeMaxDynamicSharedMemorySize, ASMEM_BYTES);

    // prep: tf32-round x and Wp; transpose+round Wq/Wk/Wv
    {
        float* xt;  cudaGetSymbolAddress((void**)&xt,  g_Xt);
        float* wpt; cudaGetSymbolAddress((void**)&wpt, g_Wpt);
        prep_round_kernel<<<(Mm * Ee) / 1024, 256>>>(x, xt);
        prep_round_kernel<<<(Ee * Ee) / 1024, 256>>>(Wp, wpt);
        dim3 gw(Ee / 32, Dh / 32, 3 * Hh);
        prep_wt_kernel<<<gw, 256>>>(Wq, Wk, Wv);
    }
    {
        dim3 grid((Hh * Dh) / 128, Mm / 128, 3);
        qkv_mma_kernel<<<grid, 256, GSMEM_BYTES>>>();
    }
    {
        dim3 grid(Tt / 128, Bb * Hh);
        attn_mma_kernel<<<grid, 256, ASMEM_BYTES>>>();
    }
    {
        dim3 grid(Ee / 128, Mm / 128);
        proj_mma_kernel<<<grid, 256, GSMEM_BYTES>>>(bp, out);
    }
}

// round 6
// speedup vs baseline: 2.7301x; 1.0179x over previous
#include <cuda_runtime.h>
#include <math.h>
#include <stdint.h>

#define Bb 8
#define Tt 1024
#define Ee 1024
#define Hh 16
#define Dh 64
#define Mm (Bb*Tt)   // 8192

// Scratch (allocation-free rule: __device__ globals)
__device__ float g_Q[Bb*Hh*Tt*Dh];
__device__ float g_K[Bb*Hh*Tt*Dh];
__device__ float g_V[Bb*Hh*Tt*Dh];
__device__ float g_Hid[Bb*Tt*Ee];
__device__ float g_Xt[Mm*Ee];        // tf32-rounded x
__device__ float g_Wt[3*Ee*Ee];      // tf32-rounded, transposed [3072][1024]
__device__ float g_Wpt[Ee*Ee];       // tf32-rounded Wp (already [n][k])

// ============================ helpers ============================
__device__ __forceinline__ uint32_t smem_u32(const void* p) {
    uint32_t a;
    asm("{ .reg .u64 t; cvta.to.shared.u64 t, %1; cvt.u32.u64 %0, t; }"
        : "=r"(a) : "l"(p));
    return a;
}
__device__ __forceinline__ uint32_t f2tf32(float x) {
    uint32_t r;
    asm("cvt.rna.tf32.f32 %0, %1;" : "=r"(r) : "f"(x));
    return r;
}
#define ST4U(addr, a, b, c, d) \
    asm volatile("st.shared.v4.b32 [%0], {%1, %2, %3, %4};" \
                 :: "r"(addr), "r"(a), "r"(b), "r"(c), "r"(d) : "memory")
#define ST2U(addr, a, b) \
    asm volatile("st.shared.v2.b32 [%0], {%1, %2};" \
                 :: "r"(addr), "r"(a), "r"(b) : "memory")
#define STS1(addr, v) \
    asm volatile("st.shared.b32 [%0], %1;" :: "r"(addr), "r"(v) : "memory")
#define LDSM_X4(r0, r1, r2, r3, addr) \
    asm volatile("ldmatrix.sync.aligned.m8n8.x4.shared.b16 {%0,%1,%2,%3}, [%4];" \
                 : "=r"(r0), "=r"(r1), "=r"(r2), "=r"(r3) : "r"(addr))
#define CP16(dst, src) \
    asm volatile("cp.async.cg.shared.global [%0], [%1], 16;" \
                 :: "r"(dst), "l"(src) : "memory")
#define CP_COMMIT() asm volatile("cp.async.commit_group;" ::: "memory")
#define CP_WAIT1()  asm volatile("cp.async.wait_group 1;" ::: "memory")
#define CP_WAIT0()  asm volatile("cp.async.wait_group 0;" ::: "memory")

__device__ __forceinline__ void mma_tf32(float* d, const uint32_t* a,
                                         uint32_t b0, uint32_t b1) {
    asm volatile(
        "mma.sync.aligned.m16n8k8.row.col.f32.tf32.tf32.f32 "
        "{%0,%1,%2,%3}, {%4,%5,%6,%7}, {%8,%9}, {%0,%1,%2,%3};"
        : "+f"(d[0]), "+f"(d[1]), "+f"(d[2]), "+f"(d[3])
        : "r"(a[0]), "r"(a[1]), "r"(a[2]), "r"(a[3]), "r"(b0), "r"(b1));
}

// ---------------------------------------------------------------------------
// Prep kernels
// ---------------------------------------------------------------------------
__global__ __launch_bounds__(256) void prep_round_kernel(
    const float* __restrict__ src, float* __restrict__ dst)
{
    const size_t i = ((size_t)blockIdx.x * 256 + threadIdx.x) * 4;
    float4 v = *(const float4*)(src + i);
    uint4 o = make_uint4(f2tf32(v.x), f2tf32(v.y), f2tf32(v.z), f2tf32(v.w));
    *(uint4*)(dst + i) = o;
}

// W[h][k][d] -> Wt[which*1024 + h*64 + d][k], tf32-rounded
__global__ __launch_bounds__(256) void prep_wt_kernel(
    const float* __restrict__ Wq, const float* __restrict__ Wk,
    const float* __restrict__ Wv)
{
    __shared__ float tile[32][33];
    const int which = blockIdx.z >> 4;
    const int h = blockIdx.z & 15;
    const float* Ws = (which == 0) ? Wq : ((which == 1) ? Wk : Wv);
    const int k0 = blockIdx.x * 32;
    const int d0 = blockIdx.y * 32;
    const int tx = threadIdx.x & 31, ty = threadIdx.x >> 5;

#pragma unroll
    for (int j = 0; j < 4; ++j) {
        const int kk = ty + j * 8;
        tile[kk][tx] = Ws[(size_t)h * (Ee * Dh) + (size_t)(k0 + kk) * Dh + d0 + tx];
    }
    __syncthreads();
#pragma unroll
    for (int j = 0; j < 4; ++j) {
        const int dd = ty + j * 8;
        const int n = h * 64 + d0 + dd;
        g_Wt[(size_t)which * (Ee * Ee) + (size_t)n * Ee + k0 + tx] =
            __uint_as_float(f2tf32(tile[tx][dd]));
    }
}

// ---------------------------------------------------------------------------
// NT tf32 GEMM: A[m][k], B rows [n][k] pre-rounded tf32. 128x128 CTA tile,
// 8 warps (2x4), warp tile 64x32, K-chunk 32, 3-stage cp.async pipeline
// (ONE __syncthreads per chunk), 2 CTAs/SM.
// MODE 0: out [B,H,T,DH] (n_out is column within the selected matrix).
// MODE 3: +bias, out [M,E].
// ---------------------------------------------------------------------------
#define GPITCH 36
#define GBUF (128*GPITCH)                    // uint32 per operand buffer
#define GSTAGE (2*GBUF*4)                    // bytes per stage (A+B)
#define GSMEM_BYTES (3*GSTAGE)               // 110592

template <int MODE>
__device__ __forceinline__ void gemm_mma_body(
    const float* __restrict__ A, const float* __restrict__ Brows,
    const float* __restrict__ bp, float* __restrict__ outp,
    int m0, int n_out)
{
    extern __shared__ uint32_t dsm[];
    const uint32_t sb = smem_u32(dsm);

    const int tid = threadIdx.x;
    const int lane = tid & 31;
    const int wid = tid >> 5;
    const int warp_m = wid & 1;
    const int warp_n = wid >> 1;

    float acc[4][4][4] = {};

    const uint32_t a_frag0 = sb +
        ((warp_m * 64 + (lane & 15)) * GPITCH + (lane >> 4) * 4) * 4;
    const uint32_t b_frag0 = sb + GBUF * 4 +
        ((warp_n * 32 + (lane & 7) + ((lane >> 4) << 3)) * GPITCH
         + ((lane >> 3) & 1) * 4) * 4;

    const int c_row = tid >> 1;
    const int c_seg = (tid & 1) * 4;

    const float* asrc0 = A + (size_t)(m0 + c_row) * Ee + c_seg * 4;
    const float* bsrc0 = Brows + (size_t)c_row * Ee + c_seg * 4;
    const uint32_t adst0 = sb + (c_row * GPITCH + c_seg * 4) * 4;

    auto copy_chunk = [&](int c, int buf) {
        const uint32_t off = (uint32_t)buf * GSTAGE;
        const int k0 = c * 32;
        const uint32_t adst = adst0 + off;
        const uint32_t bdst = adst + GBUF * 4;
#pragma unroll
        for (int j = 0; j < 4; ++j) CP16(adst + 16 * j, asrc0 + k0 + 4 * j);
#pragma unroll
        for (int j = 0; j < 4; ++j) CP16(bdst + 16 * j, bsrc0 + k0 + 4 * j);
    };

    copy_chunk(0, 0); CP_COMMIT();
    copy_chunk(1, 1); CP_COMMIT();

    int buf = 0;
    for (int c = 0; c < 32; ++c) {
        if (c < 31) CP_WAIT1(); else CP_WAIT0();
        __syncthreads();
        if (c < 30) {
            int nb = buf + 2; if (nb >= 3) nb -= 3;
            copy_chunk(c + 2, nb);
            CP_COMMIT();
        }

        const uint32_t af_b = a_frag0 + (uint32_t)buf * GSTAGE;
        const uint32_t bf_b = b_frag0 + (uint32_t)buf * GSTAGE;
#pragma unroll
        for (int ks = 0; ks < 4; ++ks) {
            uint32_t af[4][4], bf[2][4];
#pragma unroll
            for (int mt = 0; mt < 4; ++mt)
                LDSM_X4(af[mt][0], af[mt][1], af[mt][2], af[mt][3],
                        af_b + (uint32_t)(mt * 16 * GPITCH + ks * 8) * 4);
#pragma unroll
            for (int nb2 = 0; nb2 < 2; ++nb2)
                LDSM_X4(bf[nb2][0], bf[nb2][1], bf[nb2][2], bf[nb2][3],
                        bf_b + (uint32_t)(nb2 * 16 * GPITCH + ks * 8) * 4);
#pragma unroll
            for (int mt = 0; mt < 4; ++mt)
#pragma unroll
                for (int nt = 0; nt < 4; ++nt)
                    mma_tf32(acc[mt][nt], af[mt],
                             bf[nt >> 1][(nt & 1) * 2],
                             bf[nt >> 1][(nt & 1) * 2 + 1]);
        }
        if (++buf == 3) buf = 0;
    }

    // ---------------- epilogue ----------------
    const int r_base = m0 + warp_m * 64 + (lane >> 2);
    const int c_base = n_out + warp_n * 32 + (lane & 3) * 2;
#pragma unroll
    for (int mt = 0; mt < 4; ++mt) {
#pragma unroll
        for (int nt = 0; nt < 4; ++nt) {
            const int row = r_base + mt * 16;
            const int col = c_base + nt * 8;
            float2 lo = make_float2(acc[mt][nt][0], acc[mt][nt][1]);
            float2 hi = make_float2(acc[mt][nt][2], acc[mt][nt][3]);
            if (MODE == 3) {
                lo.x += bp[col]; lo.y += bp[col + 1];
                hi.x += bp[col]; hi.y += bp[col + 1];
                *(float2*)(outp + (size_t)row * Ee + col) = lo;
                *(float2*)(outp + (size_t)(row + 8) * Ee + col) = hi;
            } else {
                const int h = col >> 6, d = col & 63;
                const int b1_ = row >> 10, t1 = row & 1023;
                const int b2_ = (row + 8) >> 10, t2 = (row + 8) & 1023;
                *(float2*)(outp + (((size_t)(b1_ * Hh + h)) * Tt + t1) * Dh + d) = lo;
                *(float2*)(outp + (((size_t)(b2_ * Hh + h)) * Tt + t2) * Dh + d) = hi;
            }
        }
    }
}

// merged QKV: one GEMM 8192 x 3072 x 1024. grid (24, 64)
__global__ __launch_bounds__(256, 2) void qkv_mma_kernel()
{
    const int n0g = blockIdx.x * 128;
    const int which = n0g >> 10;
    float* outp = (which == 0) ? g_Q : ((which == 1) ? g_K : g_V);
    gemm_mma_body<0>(g_Xt, g_Wt + (size_t)n0g * Ee, nullptr, outp,
                     blockIdx.y * 128, n0g & 1023);
}

__global__ __launch_bounds__(256, 2) void proj_mma_kernel(
    const float* __restrict__ bp, float* __restrict__ out)
{
    gemm_mma_body<3>(g_Hid, g_Wpt + (size_t)blockIdx.x * 128 * Ee, bp, out,
                     blockIdx.y * 128, blockIdx.x * 128);
}

// ---------------------------------------------------------------------------
// Tensor-core causal flash attention. grid = (8 qtiles, B*H=128), block 256.
// ---------------------------------------------------------------------------
#define AQ_PITCH 68
#define AV_PITCH 132
#define ASM_QS 0
#define ASM_KS (128*AQ_PITCH*4)
#define ASM_VT (2*128*AQ_PITCH*4)
#define ASM_PW (ASM_VT + 64*AV_PITCH*4)
#define ASMEM_BYTES (ASM_PW + 8*16*AV_PITCH*4)   // 171008

__global__ __launch_bounds__(256, 1) void attn_mma_kernel()
{
    extern __shared__ uint32_t dsm[];
    const uint32_t sb = smem_u32(dsm);

    const int tid = threadIdx.x;
    const int lane = tid & 31;
    const int wid = tid >> 5;
    const int qi = blockIdx.x;
    const int bh = blockIdx.y;
    const int qm0 = qi * 128;
    const size_t base = (size_t)bh * (Tt * Dh);
    const float scale = 0.125f;

    {
        const int r = tid >> 1, c0 = (tid & 1) * 32;
        const float* qp = g_Q + base + (size_t)(qm0 + r) * Dh + c0;
        const uint32_t dst = sb + ASM_QS + (r * AQ_PITCH + c0) * 4;
#pragma unroll
        for (int j = 0; j < 8; ++j) {
            float4 v = *(const float4*)(qp + 4 * j);
            ST4U(dst + 16 * j, f2tf32(v.x), f2tf32(v.y), f2tf32(v.z), f2tf32(v.w));
        }
    }

    float m0r = -1e30f, m1r = -1e30f, l0r = 0.0f, l1r = 0.0f;
    float accO[8][4] = {};

    const uint32_t a_frag_q = sb + ASM_QS +
        ((wid * 16 + (lane & 15)) * AQ_PITCH + (lane >> 4) * 4) * 4;
    const uint32_t b_frag_k = sb + ASM_KS +
        (((lane & 7) + ((lane >> 4) << 3)) * AQ_PITCH + ((lane >> 3) & 1) * 4) * 4;
    const uint32_t b_frag_v = sb + ASM_VT +
        (((lane & 7) + ((lane >> 4) << 3)) * AV_PITCH + ((lane >> 3) & 1) * 4) * 4;
    const uint32_t pw_base = sb + ASM_PW + wid * (16 * AV_PITCH * 4);
    const uint32_t a_frag_p = pw_base +
        ((lane & 15) * AV_PITCH + (lane >> 4) * 4) * 4;
    const uint32_t p_sts = pw_base +
        ((lane >> 2) * AV_PITCH + (lane & 3) * 2) * 4;

    const int row0 = qm0 + wid * 16 + (lane >> 2);

    for (int kt = 0; kt <= qi; ++kt) {
        const int kv0 = kt * 128;
        __syncthreads();

        {
            const int r = tid >> 1, c0 = (tid & 1) * 32;
            const float* kp = g_K + base + (size_t)(kv0 + r) * Dh + c0;
            const uint32_t dst = sb + ASM_KS + (r * AQ_PITCH + c0) * 4;
#pragma unroll
            for (int j = 0; j < 8; ++j) {
                float4 v = *(const float4*)(kp + 4 * j);
                ST4U(dst + 16 * j, f2tf32(v.x), f2tf32(v.y), f2tf32(v.z), f2tf32(v.w));
            }
        }
        {
            const int key = tid & 127, dh = (tid >> 7) * 32;
            const float* vp = g_V + base + (size_t)(kv0 + key) * Dh + dh;
#pragma unroll
            for (int j = 0; j < 8; ++j) {
                float4 v = *(const float4*)(vp + 4 * j);
                const uint32_t d0 = dh + 4 * j;
                STS1(sb + ASM_VT + ((d0 + 0) * AV_PITCH + key) * 4, f2tf32(v.x));
                STS1(sb + ASM_VT + ((d0 + 1) * AV_PITCH + key) * 4, f2tf32(v.y));
                STS1(sb + ASM_VT + ((d0 + 2) * AV_PITCH + key) * 4, f2tf32(v.z));
                STS1(sb + ASM_VT + ((d0 + 3) * AV_PITCH + key) * 4, f2tf32(v.w));
            }
        }
        __syncthreads();

        float s[16][4];
#pragma unroll
        for (int i = 0; i < 16; ++i)
#pragma unroll
            for (int j = 0; j < 4; ++j) s[i][j] = 0.0f;

#pragma unroll
        for (int kc = 0; kc < 8; ++kc) {
            uint32_t aq[4];
            LDSM_X4(aq[0], aq[1], aq[2], aq[3], a_frag_q + kc * 32);
#pragma unroll
            for (int nb = 0; nb < 8; ++nb) {
                uint32_t bk[4];
                LDSM_X4(bk[0], bk[1], bk[2], bk[3],
                        b_frag_k + (uint32_t)nb * (16 * AQ_PITCH * 4) + kc * 32);
                mma_tf32(s[2 * nb],     aq, bk[0], bk[1]);
                mma_tf32(s[2 * nb + 1], aq, bk[2], bk[3]);
            }
        }

        if (kt == qi) {
#pragma unroll
            for (int nt = 0; nt < 16; ++nt) {
                const int col = kv0 + nt * 8 + (lane & 3) * 2;
                s[nt][0] = (col     <= row0)     ? s[nt][0] * scale : -1e30f;
                s[nt][1] = (col + 1 <= row0)     ? s[nt][1] * scale : -1e30f;
                s[nt][2] = (col     <= row0 + 8) ? s[nt][2] * scale : -1e30f;
                s[nt][3] = (col + 1 <= row0 + 8) ? s[nt][3] * scale : -1e30f;
            }
        } else {
#pragma unroll
            for (int nt = 0; nt < 16; ++nt) {
                s[nt][0] *= scale; s[nt][1] *= scale;
                s[nt][2] *= scale; s[nt][3] *= scale;
            }
        }

        float mx0 = -1e30f, mx1 = -1e30f;
#pragma unroll
        for (int nt = 0; nt < 16; ++nt) {
            mx0 = fmaxf(mx0, fmaxf(s[nt][0], s[nt][1]));
            mx1 = fmaxf(mx1, fmaxf(s[nt][2], s[nt][3]));
        }
        mx0 = fmaxf(mx0, __shfl_xor_sync(0xffffffffu, mx0, 1));
        mx0 = fmaxf(mx0, __shfl_xor_sync(0xffffffffu, mx0, 2));
        mx1 = fmaxf(mx1, __shfl_xor_sync(0xffffffffu, mx1, 1));
        mx1 = fmaxf(mx1, __shfl_xor_sync(0xffffffffu, mx1, 2));

        const float mn0 = fmaxf(m0r, mx0), mn1 = fmaxf(m1r, mx1);
        const float cr0 = __expf(m0r - mn0), cr1 = __expf(m1r - mn1);
        m0r = mn0; m1r = mn1;

        float sm0 = 0.0f, sm1 = 0.0f;
#pragma unroll
        for (int nt = 0; nt < 16; ++nt) {
            float p00 = __expf(s[nt][0] - mn0);
            float p01 = __expf(s[nt][1] - mn0);
            float p10 = __expf(s[nt][2] - mn1);
            float p11 = __expf(s[nt][3] - mn1);
            sm0 += p00 + p01; sm1 += p10 + p11;
            ST2U(p_sts + nt * 32, f2tf32(p00), f2tf32(p01));
            ST2U(p_sts + 8 * AV_PITCH * 4 + nt * 32, f2tf32(p10), f2tf32(p11));
        }
        sm0 += __shfl_xor_sync(0xffffffffu, sm0, 1);
        sm0 += __shfl_xor_sync(0xffffffffu, sm0, 2);
        sm1 += __shfl_xor_sync(0xffffffffu, sm1, 1);
        sm1 += __shfl_xor_sync(0xffffffffu, sm1, 2);
        l0r = l0r * cr0 + sm0;
        l1r = l1r * cr1 + sm1;

#pragma unroll
        for (int dt = 0; dt < 8; ++dt) {
            accO[dt][0] *= cr0; accO[dt][1] *= cr0;
            accO[dt][2] *= cr1; accO[dt][3] *= cr1;
        }
        __syncwarp();

#pragma unroll
        for (int kc = 0; kc < 16; ++kc) {
            uint32_t ap[4];
            LDSM_X4(ap[0], ap[1], ap[2], ap[3], a_frag_p + kc * 32);
#pragma unroll
            for (int nb = 0; nb < 4; ++nb) {
                uint32_t bv[4];
                LDSM_X4(bv[0], bv[1], bv[2], bv[3],
                        b_frag_v + (uint32_t)nb * (16 * AV_PITCH * 4) + kc * 32);
                mma_tf32(accO[2 * nb],     ap, bv[0], bv[1]);
                mma_tf32(accO[2 * nb + 1], ap, bv[2], bv[3]);
            }
        }
    }

    const float inv0 = 1.0f / l0r, inv1 = 1.0f / l1r;
    const int b = bh >> 4, h = bh & 15;
    const int t0 = row0;
#pragma unroll
    for (int dt = 0; dt < 8; ++dt) {
        const int d = dt * 8 + (lane & 3) * 2;
        float2 lo = make_float2(__uint_as_float(f2tf32(accO[dt][0] * inv0)),
                                __uint_as_float(f2tf32(accO[dt][1] * inv0)));
        float2 hi = make_float2(__uint_as_float(f2tf32(accO[dt][2] * inv1)),
                                __uint_as_float(f2tf32(accO[dt][3] * inv1)));
        *(float2*)(g_Hid + ((size_t)b * Tt + t0) * Ee + h * Dh + d) = lo;
        *(float2*)(g_Hid + ((size_t)b * Tt + t0 + 8) * Ee + h * Dh + d) = hi;
    }
}

// ---------------------------------------------------------------------------
extern "C" void kernel_launch(void* const* d_in, const int* in_sizes, int n_in,
                              void* d_out, int out_size)
{
    const float* x  = (const float*)d_in[0];
    const float* Wq = (const float*)d_in[1];
    const float* Wk = (const float*)d_in[2];
    const float* Wv = (const float*)d_in[3];
    const float* Wp = (const float*)d_in[4];
    const float* bp = (const float*)d_in[5];
    float* out = (float*)d_out;

    cudaFuncSetAttribute(qkv_mma_kernel,
                         cudaFuncAttributeMaxDynamicSharedMemorySize, GSMEM_BYTES);
    cudaFuncSetAttribute(proj_mma_kernel,
                         cudaFuncAttributeMaxDynamicSharedMemorySize, GSMEM_BYTES);
    cudaFuncSetAttribute(attn_mma_kernel,
                         cudaFuncAttributeMaxDynamicSharedMemorySize, ASMEM_BYTES);

    {
        float* xt;  cudaGetSymbolAddress((void**)&xt,  g_Xt);
        float* wpt; cudaGetSymbolAddress((void**)&wpt, g_Wpt);
        prep_round_kernel<<<(Mm * Ee) / 1024, 256>>>(x, xt);
        prep_round_kernel<<<(Ee * Ee) / 1024, 256>>>(Wp, wpt);
        dim3 gw(Ee / 32, Dh / 32, 3 * Hh);
        prep_wt_kernel<<<gw, 256>>>(Wq, Wk, Wv);
    }
    {
        dim3 grid(3 * Ee / 128, Mm / 128);
        qkv_mma_kernel<<<grid, 256, GSMEM_BYTES>>>();
    }
    {
        dim3 grid(Tt / 128, Bb * Hh);
        attn_mma_kernel<<<grid, 256, ASMEM_BYTES>>>();
    }
    {
        dim3 grid(Ee / 128, Mm / 128);
        proj_mma_kernel<<<grid, 256, GSMEM_BYTES>>>(bp, out);
    }
}

// round 7
// speedup vs baseline: 3.6020x; 1.3193x over previous
#include <cuda_runtime.h>
#include <cuda_fp16.h>
#include <math.h>
#include <stdint.h>

#define Bb 8
#define Tt 1024
#define Ee 1024
#define Hh 16
#define Dh 64
#define Mm (Bb*Tt)   // 8192

// Scratch (allocation-free rule: __device__ globals), all fp16 operands
__device__ __half g_Qh[Bb*Hh*Tt*Dh];
__device__ __half g_Kh[Bb*Hh*Tt*Dh];
__device__ __half g_Vh[Bb*Hh*Tt*Dh];
__device__ __half g_Hid[Mm*Ee];
__device__ __half g_Xh[Mm*Ee];
__device__ __half g_Wth[3*Ee*Ee];    // transposed [3072][1024]
__device__ __half g_Wph[Ee*Ee];      // Wp (already [n][k])

// ============================ helpers ============================
__device__ __forceinline__ uint32_t smem_u32(const void* p) {
    uint32_t a;
    asm("{ .reg .u64 t; cvta.to.shared.u64 t, %1; cvt.u32.u64 %0, t; }"
        : "=r"(a) : "l"(p));
    return a;
}
__device__ __forceinline__ uint32_t h2u(__half2 h) {
    return *reinterpret_cast<uint32_t*>(&h);
}
#define LDSM_X4(r0, r1, r2, r3, addr) \
    asm volatile("ldmatrix.sync.aligned.m8n8.x4.shared.b16 {%0,%1,%2,%3}, [%4];" \
                 : "=r"(r0), "=r"(r1), "=r"(r2), "=r"(r3) : "r"(addr))
#define LDSM_X4_T(r0, r1, r2, r3, addr) \
    asm volatile("ldmatrix.sync.aligned.m8n8.x4.trans.shared.b16 {%0,%1,%2,%3}, [%4];" \
                 : "=r"(r0), "=r"(r1), "=r"(r2), "=r"(r3) : "r"(addr))
#define CP16(dst, src) \
    asm volatile("cp.async.cg.shared.global [%0], [%1], 16;" \
                 :: "r"(dst), "l"(src) : "memory")
#define CP_COMMIT() asm volatile("cp.async.commit_group;" ::: "memory")
#define CP_WAIT1()  asm volatile("cp.async.wait_group 1;" ::: "memory")
#define CP_WAIT0()  asm volatile("cp.async.wait_group 0;" ::: "memory")

__device__ __forceinline__ void mma_f16(float* d, const uint32_t* a,
                                        uint32_t b0, uint32_t b1) {
    asm volatile(
        "mma.sync.aligned.m16n8k16.row.col.f32.f16.f16.f32 "
        "{%0,%1,%2,%3}, {%4,%5,%6,%7}, {%8,%9}, {%0,%1,%2,%3};"
        : "+f"(d[0]), "+f"(d[1]), "+f"(d[2]), "+f"(d[3])
        : "r"(a[0]), "r"(a[1]), "r"(a[2]), "r"(a[3]), "r"(b0), "r"(b1));
}

// ---------------------------------------------------------------------------
// Prep kernels: fp32 -> fp16 conversions (run per launch; ~70MB traffic)
// ---------------------------------------------------------------------------
__global__ __launch_bounds__(256) void prep_half_kernel(
    const float* __restrict__ src, __half* __restrict__ dst)
{
    const size_t i = ((size_t)blockIdx.x * 256 + threadIdx.x) * 4;
    float4 v = *(const float4*)(src + i);
    __half2 h0 = __floats2half2_rn(v.x, v.y);
    __half2 h1 = __floats2half2_rn(v.z, v.w);
    *(uint2*)(dst + i) = make_uint2(h2u(h0), h2u(h1));
}

// W[h][k][d] -> Wth[which*1024 + h*64 + d][k], fp16
__global__ __launch_bounds__(256) void prep_wth_kernel(
    const float* __restrict__ Wq, const float* __restrict__ Wk,
    const float* __restrict__ Wv)
{
    __shared__ float tile[32][33];
    const int which = blockIdx.z >> 4;
    const int h = blockIdx.z & 15;
    const float* Ws = (which == 0) ? Wq : ((which == 1) ? Wk : Wv);
    const int k0 = blockIdx.x * 32;
    const int d0 = blockIdx.y * 32;
    const int tx = threadIdx.x & 31, ty = threadIdx.x >> 5;

#pragma unroll
    for (int j = 0; j < 4; ++j) {
        const int kk = ty + j * 8;
        tile[kk][tx] = Ws[(size_t)h * (Ee * Dh) + (size_t)(k0 + kk) * Dh + d0 + tx];
    }
    __syncthreads();
#pragma unroll
    for (int j = 0; j < 4; ++j) {
        const int dd = ty + j * 8;
        const int n = h * 64 + d0 + dd;
        g_Wth[(size_t)which * (Ee * Ee) + (size_t)n * Ee + k0 + tx] =
            __float2half_rn(tile[tx][dd]);
    }
}

// ---------------------------------------------------------------------------
// NT fp16 GEMM: A[m][k], B rows [n][k], fp32 accum. 128x128 CTA tile,
// 8 warps (2x4), warp tile 64x32, K-chunk 64 (4 x k16), 3-stage cp.async,
// 2 CTAs/SM. MODE 0: half out, [B,H,T,DH]. MODE 3: +bias, f32 out [M,E].
// ---------------------------------------------------------------------------
#define GPITCH 72                         // halves per row
#define GBUFB (128*GPITCH*2)              // bytes per operand buffer (18432)
#define GSTAGE (2*GBUFB)                  // A+B stage (36864)
#define GSMEM_BYTES (3*GSTAGE)            // 110592

template <int MODE>
__device__ __forceinline__ void gemm_mma_body(
    const __half* __restrict__ A, const __half* __restrict__ Brows,
    const float* __restrict__ bp, void* __restrict__ outv,
    int m0, int n_out)
{
    extern __shared__ uint32_t dsm[];
    const uint32_t sb = smem_u32(dsm);

    const int tid = threadIdx.x;
    const int lane = tid & 31;
    const int wid = tid >> 5;
    const int warp_m = wid & 1;
    const int warp_n = wid >> 1;

    float acc[4][4][4] = {};

    const uint32_t a_frag0 = sb +
        ((warp_m * 64 + (lane & 15)) * GPITCH + (lane >> 4) * 8) * 2;
    const uint32_t b_frag0 = sb + GBUFB +
        ((warp_n * 32 + (lane & 7) + ((lane >> 4) << 3)) * GPITCH
         + ((lane >> 3) & 1) * 8) * 2;

    const int c_row = tid >> 1;           // 0..127
    const int c_col = (tid & 1) * 32;     // halves

    const __half* asrc0 = A + (size_t)(m0 + c_row) * Ee + c_col;
    const __half* bsrc0 = Brows + (size_t)c_row * Ee + c_col;
    const uint32_t adst0 = sb + c_row * (GPITCH * 2) + c_col * 2;

    auto copy_chunk = [&](int c, int buf) {
        const uint32_t off = (uint32_t)buf * GSTAGE;
        const int k0 = c * 64;
        const uint32_t adst = adst0 + off;
        const uint32_t bdst = adst + GBUFB;
#pragma unroll
        for (int j = 0; j < 4; ++j) CP16(adst + 16 * j, asrc0 + k0 + 8 * j);
#pragma unroll
        for (int j = 0; j < 4; ++j) CP16(bdst + 16 * j, bsrc0 + k0 + 8 * j);
    };

    copy_chunk(0, 0); CP_COMMIT();
    copy_chunk(1, 1); CP_COMMIT();

    int buf = 0;
    for (int c = 0; c < 16; ++c) {
        if (c < 15) CP_WAIT1(); else CP_WAIT0();
        __syncthreads();
        if (c < 14) {
            int nb = buf + 2; if (nb >= 3) nb -= 3;
            copy_chunk(c + 2, nb);
            CP_COMMIT();
        }

        const uint32_t af_b = a_frag0 + (uint32_t)buf * GSTAGE;
        const uint32_t bf_b = b_frag0 + (uint32_t)buf * GSTAGE;
#pragma unroll
        for (int ks = 0; ks < 4; ++ks) {
            uint32_t af[4][4], bf[2][4];
#pragma unroll
            for (int mt = 0; mt < 4; ++mt)
                LDSM_X4(af[mt][0], af[mt][1], af[mt][2], af[mt][3],
                        af_b + (uint32_t)(mt * 16 * GPITCH * 2 + ks * 32));
#pragma unroll
            for (int nb2 = 0; nb2 < 2; ++nb2)
                LDSM_X4(bf[nb2][0], bf[nb2][1], bf[nb2][2], bf[nb2][3],
                        bf_b + (uint32_t)(nb2 * 16 * GPITCH * 2 + ks * 32));
#pragma unroll
            for (int mt = 0; mt < 4; ++mt)
#pragma unroll
                for (int nt = 0; nt < 4; ++nt)
                    mma_f16(acc[mt][nt], af[mt],
                            bf[nt >> 1][(nt & 1) * 2],
                            bf[nt >> 1][(nt & 1) * 2 + 1]);
        }
        if (++buf == 3) buf = 0;
    }

    // ---------------- epilogue ----------------
    const int r_base = m0 + warp_m * 64 + (lane >> 2);
    const int c_base = n_out + warp_n * 32 + (lane & 3) * 2;
#pragma unroll
    for (int mt = 0; mt < 4; ++mt) {
#pragma unroll
        for (int nt = 0; nt < 4; ++nt) {
            const int row = r_base + mt * 16;
            const int col = c_base + nt * 8;
            if (MODE == 3) {
                float* outp = (float*)outv;
                float2 lo = make_float2(acc[mt][nt][0] + bp[col],
                                        acc[mt][nt][1] + bp[col + 1]);
                float2 hi = make_float2(acc[mt][nt][2] + bp[col],
                                        acc[mt][nt][3] + bp[col + 1]);
                *(float2*)(outp + (size_t)row * Ee + col) = lo;
                *(float2*)(outp + (size_t)(row + 8) * Ee + col) = hi;
            } else {
                __half* outp = (__half*)outv;
                const int h = col >> 6, d = col & 63;
                const int b1_ = row >> 10, t1 = row & 1023;
                const int b2_ = (row + 8) >> 10, t2 = (row + 8) & 1023;
                __half2 lo = __floats2half2_rn(acc[mt][nt][0], acc[mt][nt][1]);
                __half2 hi = __floats2half2_rn(acc[mt][nt][2], acc[mt][nt][3]);
                *(__half2*)(outp + (((size_t)(b1_ * Hh + h)) * Tt + t1) * Dh + d) = lo;
                *(__half2*)(outp + (((size_t)(b2_ * Hh + h)) * Tt + t2) * Dh + d) = hi;
            }
        }
    }
}

// merged QKV: one GEMM 8192 x 3072 x 1024. grid (24, 64)
__global__ __launch_bounds__(256, 2) void qkv_mma_kernel()
{
    const int n0g = blockIdx.x * 128;
    const int which = n0g >> 10;
    __half* outp = (which == 0) ? g_Qh : ((which == 1) ? g_Kh : g_Vh);
    gemm_mma_body<0>(g_Xh, g_Wth + (size_t)n0g * Ee, nullptr, outp,
                     blockIdx.y * 128, n0g & 1023);
}

__global__ __launch_bounds__(256, 2) void proj_mma_kernel(
    const float* __restrict__ bp, float* __restrict__ out)
{
    gemm_mma_body<3>(g_Hid, g_Wph + (size_t)blockIdx.x * 128 * Ee, bp, out,
                     blockIdx.y * 128, blockIdx.x * 128);
}

// ---------------------------------------------------------------------------
// fp16 causal flash attention (FA-2 style). grid = (8 qtiles, B*H=128),
// block 256. Warp = 16 q-rows x 128-key tile. P stays in registers
// (S-acc fragment == A fragment). V via ldmatrix.trans (no transpose stage).
// K/V double-buffered with cp.async.
// ---------------------------------------------------------------------------
#define APITCH 72
#define AQ_BYTES (128*APITCH*2)           // 18432
#define AKV_STAGE (2*AQ_BYTES)            // K+V per stage
#define ASMEM_BYTES (AQ_BYTES + 2*AKV_STAGE)  // 92160

__global__ __launch_bounds__(256, 1) void attn_mma_kernel()
{
    extern __shared__ uint32_t dsm[];
    const uint32_t sb = smem_u32(dsm);

    const int tid = threadIdx.x;
    const int lane = tid & 31;
    const int wid = tid >> 5;
    const int qi = blockIdx.x;
    const int bh = blockIdx.y;
    const int qm0 = qi * 128;
    const size_t base = (size_t)bh * (Tt * Dh);
    const float scale = 0.125f;

    const int c_row = tid >> 1;
    const int c_col = (tid & 1) * 32;
    const uint32_t cdst = c_row * (APITCH * 2) + c_col * 2;

    // Q copy (group 0, together with KV tile 0)
    {
        const __half* qp = g_Qh + base + (size_t)(qm0 + c_row) * Dh + c_col;
#pragma unroll
        for (int j = 0; j < 4; ++j) CP16(sb + cdst + 16 * j, qp + 8 * j);
    }
    auto copy_kv = [&](int kt, int buf) {
        const int kv0 = kt * 128;
        const uint32_t kb = sb + AQ_BYTES + (uint32_t)buf * AKV_STAGE;
        const __half* kp = g_Kh + base + (size_t)(kv0 + c_row) * Dh + c_col;
        const __half* vp = g_Vh + base + (size_t)(kv0 + c_row) * Dh + c_col;
#pragma unroll
        for (int j = 0; j < 4; ++j) CP16(kb + cdst + 16 * j, kp + 8 * j);
#pragma unroll
        for (int j = 0; j < 4; ++j) CP16(kb + AQ_BYTES + cdst + 16 * j, vp + 8 * j);
    };
    copy_kv(0, 0); CP_COMMIT();

    float m0r = -1e30f, m1r = -1e30f, l0r = 0.0f, l1r = 0.0f;
    float accO[8][4] = {};

    const uint32_t aq_frag = sb +
        ((wid * 16 + (lane & 15)) * APITCH + (lane >> 4) * 8) * 2;
    const uint32_t bk_off =
        (((lane & 7) + ((lane >> 4) << 3)) * APITCH + ((lane >> 3) & 1) * 8) * 2;
    const uint32_t bv_off =
        (((lane & 7) + (((lane >> 3) & 1) << 3)) * APITCH + (lane >> 4) * 8) * 2;

    const int row0 = qm0 + wid * 16 + (lane >> 2);

    for (int kt = 0; kt <= qi; ++kt) {
        const int buf = kt & 1;
        if (kt < qi) { copy_kv(kt + 1, buf ^ 1); CP_COMMIT(); CP_WAIT1(); }
        else         { CP_WAIT0(); }
        __syncthreads();

        const uint32_t kbase = sb + AQ_BYTES + (uint32_t)buf * AKV_STAGE;
        const uint32_t vbase = kbase + AQ_BYTES;
        const int kv0 = kt * 128;

        // ---- S = Q K^T : per ks(k16): 1 Q-ldsm + 8 K-ldsm + 16 mma ----
        float s[16][4];
#pragma unroll
        for (int i = 0; i < 16; ++i)
#pragma unroll
            for (int j = 0; j < 4; ++j) s[i][j] = 0.0f;

#pragma unroll
        for (int ks = 0; ks < 4; ++ks) {
            uint32_t aq[4];
            LDSM_X4(aq[0], aq[1], aq[2], aq[3], aq_frag + ks * 32);
#pragma unroll
            for (int nb = 0; nb < 8; ++nb) {
                uint32_t bk[4];
                LDSM_X4(bk[0], bk[1], bk[2], bk[3],
                        kbase + bk_off + (uint32_t)nb * (16 * APITCH * 2) + ks * 32);
                mma_f16(s[2 * nb],     aq, bk[0], bk[1]);
                mma_f16(s[2 * nb + 1], aq, bk[2], bk[3]);
            }
        }

        // ---- mask + scale ----
        if (kt == qi) {
#pragma unroll
            for (int nt = 0; nt < 16; ++nt) {
                const int col = kv0 + nt * 8 + (lane & 3) * 2;
                s[nt][0] = (col     <= row0)     ? s[nt][0] * scale : -1e30f;
                s[nt][1] = (col + 1 <= row0)     ? s[nt][1] * scale : -1e30f;
                s[nt][2] = (col     <= row0 + 8) ? s[nt][2] * scale : -1e30f;
                s[nt][3] = (col + 1 <= row0 + 8) ? s[nt][3] * scale : -1e30f;
            }
        } else {
#pragma unroll
            for (int nt = 0; nt < 16; ++nt) {
                s[nt][0] *= scale; s[nt][1] *= scale;
                s[nt][2] *= scale; s[nt][3] *= scale;
            }
        }

        // ---- online softmax (quad reductions) ----
        float mx0 = -1e30f, mx1 = -1e30f;
#pragma unroll
        for (int nt = 0; nt < 16; ++nt) {
            mx0 = fmaxf(mx0, fmaxf(s[nt][0], s[nt][1]));
            mx1 = fmaxf(mx1, fmaxf(s[nt][2], s[nt][3]));
        }
        mx0 = fmaxf(mx0, __shfl_xor_sync(0xffffffffu, mx0, 1));
        mx0 = fmaxf(mx0, __shfl_xor_sync(0xffffffffu, mx0, 2));
        mx1 = fmaxf(mx1, __shfl_xor_sync(0xffffffffu, mx1, 1));
        mx1 = fmaxf(mx1, __shfl_xor_sync(0xffffffffu, mx1, 2));

        const float mn0 = fmaxf(m0r, mx0), mn1 = fmaxf(m1r, mx1);
        const float cr0 = __expf(m0r - mn0), cr1 = __expf(m1r - mn1);
        m0r = mn0; m1r = mn1;

        // exp -> P as half2 A-fragments (no smem round-trip)
        uint32_t ph[16][2];
        float sm0 = 0.0f, sm1 = 0.0f;
#pragma unroll
        for (int nt = 0; nt < 16; ++nt) {
            float p00 = __expf(s[nt][0] - mn0);
            float p01 = __expf(s[nt][1] - mn0);
            float p10 = __expf(s[nt][2] - mn1);
            float p11 = __expf(s[nt][3] - mn1);
            sm0 += p00 + p01; sm1 += p10 + p11;
            ph[nt][0] = h2u(__floats2half2_rn(p00, p01));
            ph[nt][1] = h2u(__floats2half2_rn(p10, p11));
        }
        sm0 += __shfl_xor_sync(0xffffffffu, sm0, 1);
        sm0 += __shfl_xor_sync(0xffffffffu, sm0, 2);
        sm1 += __shfl_xor_sync(0xffffffffu, sm1, 1);
        sm1 += __shfl_xor_sync(0xffffffffu, sm1, 2);
        l0r = l0r * cr0 + sm0;
        l1r = l1r * cr1 + sm1;

#pragma unroll
        for (int dt = 0; dt < 8; ++dt) {
            accO[dt][0] *= cr0; accO[dt][1] *= cr0;
            accO[dt][2] *= cr1; accO[dt][3] *= cr1;
        }

        // ---- O += P V : 8 key-slices x (4 V-ldsm.trans + 8 mma) ----
#pragma unroll
        for (int j = 0; j < 8; ++j) {
            uint32_t a[4] = { ph[2 * j][0], ph[2 * j][1],
                              ph[2 * j + 1][0], ph[2 * j + 1][1] };
#pragma unroll
            for (int dt = 0; dt < 4; ++dt) {
                uint32_t bv[4];
                LDSM_X4_T(bv[0], bv[1], bv[2], bv[3],
                          vbase + bv_off + (uint32_t)j * (16 * APITCH * 2) + dt * 32);
                mma_f16(accO[2 * dt],     a, bv[0], bv[1]);
                mma_f16(accO[2 * dt + 1], a, bv[2], bv[3]);
            }
        }
        __syncthreads();   // all warps done with this KV buffer
    }

    // ---- normalize + write g_Hid (half) [B, T, H*DH] ----
    const float inv0 = 1.0f / l0r, inv1 = 1.0f / l1r;
    const int b = bh >> 4, h = bh & 15;
    const int t0 = row0;
#pragma unroll
    for (int dt = 0; dt < 8; ++dt) {
        const int d = dt * 8 + (lane & 3) * 2;
        __half2 lo = __floats2half2_rn(accO[dt][0] * inv0, accO[dt][1] * inv0);
        __half2 hi = __floats2half2_rn(accO[dt][2] * inv1, accO[dt][3] * inv1);
        *(__half2*)(g_Hid + ((size_t)b * Tt + t0) * Ee + h * Dh + d) = lo;
        *(__half2*)(g_Hid + ((size_t)b * Tt + t0 + 8) * Ee + h * Dh + d) = hi;
    }
}

// ---------------------------------------------------------------------------
extern "C" void kernel_launch(void* const* d_in, const int* in_sizes, int n_in,
                              void* d_out, int out_size)
{
    const float* x  = (const float*)d_in[0];
    const float* Wq = (const float*)d_in[1];
    const float* Wk = (const float*)d_in[2];
    const float* Wv = (const float*)d_in[3];
    const float* Wp = (const float*)d_in[4];
    const float* bp = (const float*)d_in[5];
    float* out = (float*)d_out;

    cudaFuncSetAttribute(qkv_mma_kernel,
                         cudaFuncAttributeMaxDynamicSharedMemorySize, GSMEM_BYTES);
    cudaFuncSetAttribute(proj_mma_kernel,
                         cudaFuncAttributeMaxDynamicSharedMemorySize, GSMEM_BYTES);
    cudaFuncSetAttribute(attn_mma_kernel,
                         cudaFuncAttributeMaxDynamicSharedMemorySize, ASMEM_BYTES);

    {
        __half* xh;  cudaGetSymbolAddress((void**)&xh,  g_Xh);
        __half* wph; cudaGetSymbolAddress((void**)&wph, g_Wph);
        prep_half_kernel<<<(Mm * Ee) / 1024, 256>>>(x, xh);
        prep_half_kernel<<<(Ee * Ee) / 1024, 256>>>(Wp, wph);
        dim3 gw(Ee / 32, Dh / 32, 3 * Hh);
        prep_wth_kernel<<<gw, 256>>>(Wq, Wk, Wv);
    }
    {
        dim3 grid(3 * Ee / 128, Mm / 128);
        qkv_mma_kernel<<<grid, 256, GSMEM_BYTES>>>();
    }
    {
        dim3 grid(Tt / 128, Bb * Hh);
        attn_mma_kernel<<<grid, 256, ASMEM_BYTES>>>();
    }
    {
        dim3 grid(Ee / 128, Mm / 128);
        proj_mma_kernel<<<grid, 256, GSMEM_BYTES>>>(bp, out);
    }
}

// round 8
// speedup vs baseline: 4.8327x; 1.3417x over previous
#include <cuda_runtime.h>
#include <cuda_fp16.h>
#include <math.h>
#include <stdint.h>

#define Bb 8
#define Tt 1024
#define Ee 1024
#define Hh 16
#define Dh 64
#define Mm (Bb*Tt)   // 8192

// Scratch (allocation-free rule: __device__ globals), all fp16 operands
__device__ __half g_Qh[Bb*Hh*Tt*Dh];
__device__ __half g_Kh[Bb*Hh*Tt*Dh];
__device__ __half g_Vh[Bb*Hh*Tt*Dh];
__device__ __half g_Hid[Mm*Ee];
__device__ __half g_Xh[Mm*Ee];
__device__ __half g_Wth[3*Ee*Ee];    // transposed [3072][1024]
__device__ __half g_Wph[Ee*Ee];      // Wp (already [n][k])

// ============================ helpers ============================
__device__ __forceinline__ uint32_t smem_u32(const void* p) {
    uint32_t a;
    asm("{ .reg .u64 t; cvta.to.shared.u64 t, %1; cvt.u32.u64 %0, t; }"
        : "=r"(a) : "l"(p));
    return a;
}
__device__ __forceinline__ uint32_t h2u(__half2 h) {
    return *reinterpret_cast<uint32_t*>(&h);
}
#define LDSM_X4(r0, r1, r2, r3, addr) \
    asm volatile("ldmatrix.sync.aligned.m8n8.x4.shared.b16 {%0,%1,%2,%3}, [%4];" \
                 : "=r"(r0), "=r"(r1), "=r"(r2), "=r"(r3) : "r"(addr))
#define LDSM_X4_T(r0, r1, r2, r3, addr) \
    asm volatile("ldmatrix.sync.aligned.m8n8.x4.trans.shared.b16 {%0,%1,%2,%3}, [%4];" \
                 : "=r"(r0), "=r"(r1), "=r"(r2), "=r"(r3) : "r"(addr))
#define CP16(dst, src) \
    asm volatile("cp.async.cg.shared.global [%0], [%1], 16;" \
                 :: "r"(dst), "l"(src) : "memory")
#define CP_COMMIT() asm volatile("cp.async.commit_group;" ::: "memory")
#define CP_WAIT1()  asm volatile("cp.async.wait_group 1;" ::: "memory")
#define CP_WAIT0()  asm volatile("cp.async.wait_group 0;" ::: "memory")

__device__ __forceinline__ void mma_f16(float* d, const uint32_t* a,
                                        uint32_t b0, uint32_t b1) {
    asm volatile(
        "mma.sync.aligned.m16n8k16.row.col.f32.f16.f16.f32 "
        "{%0,%1,%2,%3}, {%4,%5,%6,%7}, {%8,%9}, {%0,%1,%2,%3};"
        : "+f"(d[0]), "+f"(d[1]), "+f"(d[2]), "+f"(d[3])
        : "r"(a[0]), "r"(a[1]), "r"(a[2]), "r"(a[3]), "r"(b0), "r"(b1));
}

// ---------------------------------------------------------------------------
// Prep kernels: fp32 -> fp16 conversions
// ---------------------------------------------------------------------------
__global__ __launch_bounds__(256) void prep_half_kernel(
    const float* __restrict__ src, __half* __restrict__ dst)
{
    const size_t i = ((size_t)blockIdx.x * 256 + threadIdx.x) * 4;
    float4 v = *(const float4*)(src + i);
    __half2 h0 = __floats2half2_rn(v.x, v.y);
    __half2 h1 = __floats2half2_rn(v.z, v.w);
    *(uint2*)(dst + i) = make_uint2(h2u(h0), h2u(h1));
}

// W[h][k][d] -> Wth[which*1024 + h*64 + d][k], fp16
__global__ __launch_bounds__(256) void prep_wth_kernel(
    const float* __restrict__ Wq, const float* __restrict__ Wk,
    const float* __restrict__ Wv)
{
    __shared__ float tile[32][33];
    const int which = blockIdx.z >> 4;
    const int h = blockIdx.z & 15;
    const float* Ws = (which == 0) ? Wq : ((which == 1) ? Wk : Wv);
    const int k0 = blockIdx.x * 32;
    const int d0 = blockIdx.y * 32;
    const int tx = threadIdx.x & 31, ty = threadIdx.x >> 5;

#pragma unroll
    for (int j = 0; j < 4; ++j) {
        const int kk = ty + j * 8;
        tile[kk][tx] = Ws[(size_t)h * (Ee * Dh) + (size_t)(k0 + kk) * Dh + d0 + tx];
    }
    __syncthreads();
#pragma unroll
    for (int j = 0; j < 4; ++j) {
        const int dd = ty + j * 8;
        const int n = h * 64 + d0 + dd;
        g_Wth[(size_t)which * (Ee * Ee) + (size_t)n * Ee + k0 + tx] =
            __float2half_rn(tile[tx][dd]);
    }
}

// ---------------------------------------------------------------------------
// NT fp16 GEMM, fp32 accum. 128x128 CTA tile, 8 warps (2x4), warp 64x32,
// K-chunk 64, 3-stage cp.async, REGISTER fragment double-buffering
// (LDSM of ks+1 overlaps MMA of ks). 1 CTA/SM (regs > 128).
// MODE 0: half out [B,H,T,DH].  MODE 3: +bias, f32 out [M,E].
// ---------------------------------------------------------------------------
#define GPITCH 72                         // halves per row
#define GBUFB (128*GPITCH*2)              // bytes per operand buffer (18432)
#define GSTAGE (2*GBUFB)                  // A+B stage (36864)
#define GSMEM_BYTES (3*GSTAGE)            // 110592

template <int MODE>
__device__ __forceinline__ void gemm_mma_body(
    const __half* __restrict__ A, const __half* __restrict__ Brows,
    const float* __restrict__ bp, void* __restrict__ outv,
    int m0, int n_out)
{
    extern __shared__ uint32_t dsm[];
    const uint32_t sb = smem_u32(dsm);

    const int tid = threadIdx.x;
    const int lane = tid & 31;
    const int wid = tid >> 5;
    const int warp_m = wid & 1;
    const int warp_n = wid >> 1;

    float acc[4][4][4] = {};

    const uint32_t a_frag0 = sb +
        ((warp_m * 64 + (lane & 15)) * GPITCH + (lane >> 4) * 8) * 2;
    const uint32_t b_frag0 = sb + GBUFB +
        ((warp_n * 32 + (lane & 7) + ((lane >> 4) << 3)) * GPITCH
         + ((lane >> 3) & 1) * 8) * 2;

    const int c_row = tid >> 1;           // 0..127
    const int c_col = (tid & 1) * 32;     // halves

    const __half* asrc0 = A + (size_t)(m0 + c_row) * Ee + c_col;
    const __half* bsrc0 = Brows + (size_t)c_row * Ee + c_col;
    const uint32_t adst0 = sb + c_row * (GPITCH * 2) + c_col * 2;

    auto copy_chunk = [&](int c, int buf) {
        const uint32_t off = (uint32_t)buf * GSTAGE;
        const int k0 = c * 64;
        const uint32_t adst = adst0 + off;
        const uint32_t bdst = adst + GBUFB;
#pragma unroll
        for (int j = 0; j < 4; ++j) CP16(adst + 16 * j, asrc0 + k0 + 8 * j);
#pragma unroll
        for (int j = 0; j < 4; ++j) CP16(bdst + 16 * j, bsrc0 + k0 + 8 * j);
    };

    copy_chunk(0, 0); CP_COMMIT();
    copy_chunk(1, 1); CP_COMMIT();

    // register fragment double buffer
    uint32_t af[2][4][4], bf[2][2][4];

    int buf = 0;
    for (int c = 0; c < 16; ++c) {
        if (c < 15) CP_WAIT1(); else CP_WAIT0();
        __syncthreads();
        if (c < 14) {
            int nb = buf + 2; if (nb >= 3) nb -= 3;
            copy_chunk(c + 2, nb);
            CP_COMMIT();
        }

        const uint32_t af_b = a_frag0 + (uint32_t)buf * GSTAGE;
        const uint32_t bf_b = b_frag0 + (uint32_t)buf * GSTAGE;

        // preload ks=0 fragments
#pragma unroll
        for (int mt = 0; mt < 4; ++mt)
            LDSM_X4(af[0][mt][0], af[0][mt][1], af[0][mt][2], af[0][mt][3],
                    af_b + (uint32_t)(mt * 16 * GPITCH * 2));
#pragma unroll
        for (int nb2 = 0; nb2 < 2; ++nb2)
            LDSM_X4(bf[0][nb2][0], bf[0][nb2][1], bf[0][nb2][2], bf[0][nb2][3],
                    bf_b + (uint32_t)(nb2 * 16 * GPITCH * 2));

#pragma unroll
        for (int ks = 0; ks < 4; ++ks) {
            const int cur = ks & 1, nxt = cur ^ 1;
            if (ks < 3) {   // prefetch ks+1 fragments during MMAs
#pragma unroll
                for (int mt = 0; mt < 4; ++mt)
                    LDSM_X4(af[nxt][mt][0], af[nxt][mt][1],
                            af[nxt][mt][2], af[nxt][mt][3],
                            af_b + (uint32_t)(mt * 16 * GPITCH * 2 + (ks + 1) * 32));
#pragma unroll
                for (int nb2 = 0; nb2 < 2; ++nb2)
                    LDSM_X4(bf[nxt][nb2][0], bf[nxt][nb2][1],
                            bf[nxt][nb2][2], bf[nxt][nb2][3],
                            bf_b + (uint32_t)(nb2 * 16 * GPITCH * 2 + (ks + 1) * 32));
            }
#pragma unroll
            for (int mt = 0; mt < 4; ++mt)
#pragma unroll
                for (int nt = 0; nt < 4; ++nt)
                    mma_f16(acc[mt][nt], af[cur][mt],
                            bf[cur][nt >> 1][(nt & 1) * 2],
                            bf[cur][nt >> 1][(nt & 1) * 2 + 1]);
        }
        if (++buf == 3) buf = 0;
    }

    // ---------------- epilogue ----------------
    const int r_base = m0 + warp_m * 64 + (lane >> 2);
    const int c_base = n_out + warp_n * 32 + (lane & 3) * 2;
#pragma unroll
    for (int mt = 0; mt < 4; ++mt) {
#pragma unroll
        for (int nt = 0; nt < 4; ++nt) {
            const int row = r_base + mt * 16;
            const int col = c_base + nt * 8;
            if (MODE == 3) {
                float* outp = (float*)outv;
                float2 lo = make_float2(acc[mt][nt][0] + bp[col],
                                        acc[mt][nt][1] + bp[col + 1]);
                float2 hi = make_float2(acc[mt][nt][2] + bp[col],
                                        acc[mt][nt][3] + bp[col + 1]);
                *(float2*)(outp + (size_t)row * Ee + col) = lo;
                *(float2*)(outp + (size_t)(row + 8) * Ee + col) = hi;
            } else {
                __half* outp = (__half*)outv;
                const int h = col >> 6, d = col & 63;
                const int b1_ = row >> 10, t1 = row & 1023;
                const int b2_ = (row + 8) >> 10, t2 = (row + 8) & 1023;
                __half2 lo = __floats2half2_rn(acc[mt][nt][0], acc[mt][nt][1]);
                __half2 hi = __floats2half2_rn(acc[mt][nt][2], acc[mt][nt][3]);
                *(__half2*)(outp + (((size_t)(b1_ * Hh + h)) * Tt + t1) * Dh + d) = lo;
                *(__half2*)(outp + (((size_t)(b2_ * Hh + h)) * Tt + t2) * Dh + d) = hi;
            }
        }
    }
}

// merged QKV: one GEMM 8192 x 3072 x 1024. grid (24, 64)
__global__ __launch_bounds__(256, 1) void qkv_mma_kernel()
{
    const int n0g = blockIdx.x * 128;
    const int which = n0g >> 10;
    __half* outp = (which == 0) ? g_Qh : ((which == 1) ? g_Kh : g_Vh);
    gemm_mma_body<0>(g_Xh, g_Wth + (size_t)n0g * Ee, nullptr, outp,
                     blockIdx.y * 128, n0g & 1023);
}

__global__ __launch_bounds__(256, 1) void proj_mma_kernel(
    const float* __restrict__ bp, float* __restrict__ out)
{
    gemm_mma_body<3>(g_Hid, g_Wph + (size_t)blockIdx.x * 128 * Ee, bp, out,
                     blockIdx.y * 128, blockIdx.x * 128);
}

// ---------------------------------------------------------------------------
// fp16 causal flash attention (FA-2 style, unchanged from R7).
// grid = (8 qtiles, B*H=128), block 256.
// ---------------------------------------------------------------------------
#define APITCH 72
#define AQ_BYTES (128*APITCH*2)           // 18432
#define AKV_STAGE (2*AQ_BYTES)            // K+V per stage
#define ASMEM_BYTES (AQ_BYTES + 2*AKV_STAGE)  // 92160

__global__ __launch_bounds__(256, 1) void attn_mma_kernel()
{
    extern __shared__ uint32_t dsm[];
    const uint32_t sb = smem_u32(dsm);

    const int tid = threadIdx.x;
    const int lane = tid & 31;
    const int wid = tid >> 5;
    const int qi = blockIdx.x;
    const int bh = blockIdx.y;
    const int qm0 = qi * 128;
    const size_t base = (size_t)bh * (Tt * Dh);
    const float scale = 0.125f;

    const int c_row = tid >> 1;
    const int c_col = (tid & 1) * 32;
    const uint32_t cdst = c_row * (APITCH * 2) + c_col * 2;

    {
        const __half* qp = g_Qh + base + (size_t)(qm0 + c_row) * Dh + c_col;
#pragma unroll
        for (int j = 0; j < 4; ++j) CP16(sb + cdst + 16 * j, qp + 8 * j);
    }
    auto copy_kv = [&](int kt, int buf) {
        const int kv0 = kt * 128;
        const uint32_t kb = sb + AQ_BYTES + (uint32_t)buf * AKV_STAGE;
        const __half* kp = g_Kh + base + (size_t)(kv0 + c_row) * Dh + c_col;
        const __half* vp = g_Vh + base + (size_t)(kv0 + c_row) * Dh + c_col;
#pragma unroll
        for (int j = 0; j < 4; ++j) CP16(kb + cdst + 16 * j, kp + 8 * j);
#pragma unroll
        for (int j = 0; j < 4; ++j) CP16(kb + AQ_BYTES + cdst + 16 * j, vp + 8 * j);
    };
    copy_kv(0, 0); CP_COMMIT();

    float m0r = -1e30f, m1r = -1e30f, l0r = 0.0f, l1r = 0.0f;
    float accO[8][4] = {};

    const uint32_t aq_frag = sb +
        ((wid * 16 + (lane & 15)) * APITCH + (lane >> 4) * 8) * 2;
    const uint32_t bk_off =
        (((lane & 7) + ((lane >> 4) << 3)) * APITCH + ((lane >> 3) & 1) * 8) * 2;
    const uint32_t bv_off =
        (((lane & 7) + (((lane >> 3) & 1) << 3)) * APITCH + (lane >> 4) * 8) * 2;

    const int row0 = qm0 + wid * 16 + (lane >> 2);

    for (int kt = 0; kt <= qi; ++kt) {
        const int buf = kt & 1;
        if (kt < qi) { copy_kv(kt + 1, buf ^ 1); CP_COMMIT(); CP_WAIT1(); }
        else         { CP_WAIT0(); }
        __syncthreads();

        const uint32_t kbase = sb + AQ_BYTES + (uint32_t)buf * AKV_STAGE;
        const uint32_t vbase = kbase + AQ_BYTES;
        const int kv0 = kt * 128;

        float s[16][4];
#pragma unroll
        for (int i = 0; i < 16; ++i)
#pragma unroll
            for (int j = 0; j < 4; ++j) s[i][j] = 0.0f;

#pragma unroll
        for (int ks = 0; ks < 4; ++ks) {
            uint32_t aq[4];
            LDSM_X4(aq[0], aq[1], aq[2], aq[3], aq_frag + ks * 32);
#pragma unroll
            for (int nb = 0; nb < 8; ++nb) {
                uint32_t bk[4];
                LDSM_X4(bk[0], bk[1], bk[2], bk[3],
                        kbase + bk_off + (uint32_t)nb * (16 * APITCH * 2) + ks * 32);
                mma_f16(s[2 * nb],     aq, bk[0], bk[1]);
                mma_f16(s[2 * nb + 1], aq, bk[2], bk[3]);
            }
        }

        if (kt == qi) {
#pragma unroll
            for (int nt = 0; nt < 16; ++nt) {
                const int col = kv0 + nt * 8 + (lane & 3) * 2;
                s[nt][0] = (col     <= row0)     ? s[nt][0] * scale : -1e30f;
                s[nt][1] = (col + 1 <= row0)     ? s[nt][1] * scale : -1e30f;
                s[nt][2] = (col     <= row0 + 8) ? s[nt][2] * scale : -1e30f;
                s[nt][3] = (col + 1 <= row0 + 8) ? s[nt][3] * scale : -1e30f;
            }
        } else {
#pragma unroll
            for (int nt = 0; nt < 16; ++nt) {
                s[nt][0] *= scale; s[nt][1] *= scale;
                s[nt][2] *= scale; s[nt][3] *= scale;
            }
        }

        float mx0 = -1e30f, mx1 = -1e30f;
#pragma unroll
        for (int nt = 0; nt < 16; ++nt) {
            mx0 = fmaxf(mx0, fmaxf(s[nt][0], s[nt][1]));
            mx1 = fmaxf(mx1, fmaxf(s[nt][2], s[nt][3]));
        }
        mx0 = fmaxf(mx0, __shfl_xor_sync(0xffffffffu, mx0, 1));
        mx0 = fmaxf(mx0, __shfl_xor_sync(0xffffffffu, mx0, 2));
        mx1 = fmaxf(mx1, __shfl_xor_sync(0xffffffffu, mx1, 1));
        mx1 = fmaxf(mx1, __shfl_xor_sync(0xffffffffu, mx1, 2));

        const float mn0 = fmaxf(m0r, mx0), mn1 = fmaxf(m1r, mx1);
        const float cr0 = __expf(m0r - mn0), cr1 = __expf(m1r - mn1);
        m0r = mn0; m1r = mn1;

        uint32_t ph[16][2];
        float sm0 = 0.0f, sm1 = 0.0f;
#pragma unroll
        for (int nt = 0; nt < 16; ++nt) {
            float p00 = __expf(s[nt][0] - mn0);
            float p01 = __expf(s[nt][1] - mn0);
            float p10 = __expf(s[nt][2] - mn1);
            float p11 = __expf(s[nt][3] - mn1);
            sm0 += p00 + p01; sm1 += p10 + p11;
            ph[nt][0] = h2u(__floats2half2_rn(p00, p01));
            ph[nt][1] = h2u(__floats2half2_rn(p10, p11));
        }
        sm0 += __shfl_xor_sync(0xffffffffu, sm0, 1);
        sm0 += __shfl_xor_sync(0xffffffffu, sm0, 2);
        sm1 += __shfl_xor_sync(0xffffffffu, sm1, 1);
        sm1 += __shfl_xor_sync(0xffffffffu, sm1, 2);
        l0r = l0r * cr0 + sm0;
        l1r = l1r * cr1 + sm1;

#pragma unroll
        for (int dt = 0; dt < 8; ++dt) {
            accO[dt][0] *= cr0; accO[dt][1] *= cr0;
            accO[dt][2] *= cr1; accO[dt][3] *= cr1;
        }

#pragma unroll
        for (int j = 0; j < 8; ++j) {
            uint32_t a[4] = { ph[2 * j][0], ph[2 * j][1],
                              ph[2 * j + 1][0], ph[2 * j + 1][1] };
#pragma unroll
            for (int dt = 0; dt < 4; ++dt) {
                uint32_t bv[4];
                LDSM_X4_T(bv[0], bv[1], bv[2], bv[3],
                          vbase + bv_off + (uint32_t)j * (16 * APITCH * 2) + dt * 32);
                mma_f16(accO[2 * dt],     a, bv[0], bv[1]);
                mma_f16(accO[2 * dt + 1], a, bv[2], bv[3]);
            }
        }
        __syncthreads();
    }

    const float inv0 = 1.0f / l0r, inv1 = 1.0f / l1r;
    const int b = bh >> 4, h = bh & 15;
    const int t0 = row0;
#pragma unroll
    for (int dt = 0; dt < 8; ++dt) {
        const int d = dt * 8 + (lane & 3) * 2;
        __half2 lo = __floats2half2_rn(accO[dt][0] * inv0, accO[dt][1] * inv0);
        __half2 hi = __floats2half2_rn(accO[dt][2] * inv1, accO[dt][3] * inv1);
        *(__half2*)(g_Hid + ((size_t)b * Tt + t0) * Ee + h * Dh + d) = lo;
        *(__half2*)(g_Hid + ((size_t)b * Tt + t0 + 8) * Ee + h * Dh + d) = hi;
    }
}

// ---------------------------------------------------------------------------
extern "C" void kernel_launch(void* const* d_in, const int* in_sizes, int n_in,
                              void* d_out, int out_size)
{
    const float* x  = (const float*)d_in[0];
    const float* Wq = (const float*)d_in[1];
    const float* Wk = (const float*)d_in[2];
    const float* Wv = (const float*)d_in[3];
    const float* Wp = (const float*)d_in[4];
    const float* bp = (const float*)d_in[5];
    float* out = (float*)d_out;

    cudaFuncSetAttribute(qkv_mma_kernel,
                         cudaFuncAttributeMaxDynamicSharedMemorySize, GSMEM_BYTES);
    cudaFuncSetAttribute(proj_mma_kernel,
                         cudaFuncAttributeMaxDynamicSharedMemorySize, GSMEM_BYTES);
    cudaFuncSetAttribute(attn_mma_kernel,
                         cudaFuncAttributeMaxDynamicSharedMemorySize, ASMEM_BYTES);

    {
        __half* xh;  cudaGetSymbolAddress((void**)&xh,  g_Xh);
        __half* wph; cudaGetSymbolAddress((void**)&wph, g_Wph);
        prep_half_kernel<<<(Mm * Ee) / 1024, 256>>>(x, xh);
        prep_half_kernel<<<(Ee * Ee) / 1024, 256>>>(Wp, wph);
        dim3 gw(Ee / 32, Dh / 32, 3 * Hh);
        prep_wth_kernel<<<gw, 256>>>(Wq, Wk, Wv);
    }
    {
        dim3 grid(3 * Ee / 128, Mm / 128);
        qkv_mma_kernel<<<grid, 256, GSMEM_BYTES>>>();
    }
    {
        dim3 grid(Tt / 128, Bb * Hh);
        attn_mma_kernel<<<grid, 256, ASMEM_BYTES>>>();
    }
    {
        dim3 grid(Ee / 128, Mm / 128);
        proj_mma_kernel<<<grid, 256, GSMEM_BYTES>>>(bp, out);
    }
}